// round 2
// baseline (speedup 1.0000x reference)
#include <cuda_runtime.h>
#include <cstdint>

#define B_   8
#define T_   1024
#define D_   1280
#define H_   20
#define DH_  64
#define MTOT (B_ * T_)   // 8192

// Scratch (device globals; no allocation allowed)
__device__ float g_Q[(size_t)MTOT * D_];
__device__ float g_WV[(size_t)MTOT * D_];

// ---------------------------------------------------------------------------
// GEMM: C[M x N] = A[M x K] @ W[K x N] (+ bias), M=8192, N=K=1280
// Block tile 128x128, BK=8, 256 threads, 8x8 per-thread (split 4+4).
// ---------------------------------------------------------------------------
__global__ __launch_bounds__(256) void gemm_bias_kernel(
    const float* __restrict__ A, const float* __restrict__ W,
    const float* __restrict__ bias, float* __restrict__ C)
{
    const int K = D_, N = D_;
    __shared__ float As[8][132];   // transposed A tile, +4 pad
    __shared__ float Bs[8][128];

    const int tid = threadIdx.x;
    const int tx = tid & 15;
    const int ty = tid >> 4;
    const int bm = blockIdx.y * 128;
    const int bn = blockIdx.x * 128;

    float acc[8][8];
#pragma unroll
    for (int i = 0; i < 8; i++)
#pragma unroll
        for (int j = 0; j < 8; j++) acc[i][j] = 0.f;

    const int arow = tid >> 1;          // 0..127
    const int acol = (tid & 1) * 4;     // 0 or 4
    const int brow = tid >> 5;          // 0..7
    const int bcol = (tid & 31) * 4;    // 0..124
    const float* Ag = A + (size_t)(bm + arow) * K + acol;
    const float* Wg = W + (size_t)brow * N + bn + bcol;

    for (int k0 = 0; k0 < K; k0 += 8) {
        float4 av = *(const float4*)(Ag + k0);
        float4 wv = *(const float4*)(Wg + (size_t)k0 * N);
        __syncthreads();
        As[acol + 0][arow] = av.x;
        As[acol + 1][arow] = av.y;
        As[acol + 2][arow] = av.z;
        As[acol + 3][arow] = av.w;
        *(float4*)&Bs[brow][bcol] = wv;
        __syncthreads();
#pragma unroll
        for (int kk = 0; kk < 8; kk++) {
            float a[8], b[8];
            *(float4*)&a[0] = *(const float4*)&As[kk][ty * 4];
            *(float4*)&a[4] = *(const float4*)&As[kk][64 + ty * 4];
            *(float4*)&b[0] = *(const float4*)&Bs[kk][tx * 4];
            *(float4*)&b[4] = *(const float4*)&Bs[kk][64 + tx * 4];
#pragma unroll
            for (int i = 0; i < 8; i++)
#pragma unroll
                for (int j = 0; j < 8; j++)
                    acc[i][j] = fmaf(a[i], b[j], acc[i][j]);
        }
    }

    float bv[8];
#pragma unroll
    for (int j = 0; j < 8; j++) {
        int col = bn + ((j < 4) ? (tx * 4 + j) : (64 + tx * 4 + (j - 4)));
        bv[j] = bias ? bias[col] : 0.f;
    }
#pragma unroll
    for (int i = 0; i < 8; i++) {
        int row = bm + ((i < 4) ? (ty * 4 + i) : (64 + ty * 4 + (i - 4)));
        float4 lo, hi;
        lo.x = acc[i][0] + bv[0]; lo.y = acc[i][1] + bv[1];
        lo.z = acc[i][2] + bv[2]; lo.w = acc[i][3] + bv[3];
        hi.x = acc[i][4] + bv[4]; hi.y = acc[i][5] + bv[5];
        hi.z = acc[i][6] + bv[6]; hi.w = acc[i][7] + bv[7];
        *(float4*)(C + (size_t)row * N + bn + tx * 4)      = lo;
        *(float4*)(C + (size_t)row * N + bn + 64 + tx * 4) = hi;
    }
}

// ---------------------------------------------------------------------------
// Causal flash attention, fp32. One block = one (b,h) x 64 q-rows.
// 256 threads as 16x16; 4x4 frags. Row stride in smem = 68 floats
// (16B-aligned float4 everywhere; <=2-way bank conflicts).
// ---------------------------------------------------------------------------
#define STR 68

__global__ __launch_bounds__(256) void attn_kernel(
    const float* __restrict__ Q, const float* __restrict__ Kc,
    const float* __restrict__ Vc, float* __restrict__ O)
{
    extern __shared__ float smf[];
    float* qs = smf;                 // [64][STR]
    float* ks = smf + 64 * STR;
    float* vs = smf + 2 * 64 * STR;
    float* ps = smf + 3 * 64 * STR;

    const int tid = threadIdx.x;
    const int tx = tid & 15;
    const int ty = tid >> 4;
    const int bh = blockIdx.x;
    const int b  = bh / H_;
    const int h  = bh % H_;
    const int qt = blockIdx.y;
    const float scale = 0.125f;      // DH^-0.5

    // Load q tile (scaled)
    const float* qg = Q + (size_t)(b * T_ + qt * 64) * D_ + h * 64;
    for (int i = tid; i < 64 * 16; i += 256) {
        int r = i >> 4, c = (i & 15) * 4;
        float4 v = *(const float4*)(qg + (size_t)r * D_ + c);
        qs[r * STR + c + 0] = v.x * scale;
        qs[r * STR + c + 1] = v.y * scale;
        qs[r * STR + c + 2] = v.z * scale;
        qs[r * STR + c + 3] = v.w * scale;
    }

    float m[4], l[4], o[4][4];
#pragma unroll
    for (int i = 0; i < 4; i++) {
        m[i] = -1e30f; l[i] = 0.f;
#pragma unroll
        for (int j = 0; j < 4; j++) o[i][j] = 0.f;
    }

    for (int kt = 0; kt <= qt; kt++) {
        const float* kg = Kc + (size_t)(b * T_ + kt * 64) * D_ + h * 64;
        const float* vg = Vc + (size_t)(b * T_ + kt * 64) * D_ + h * 64;
        __syncthreads();   // previous PV done before overwriting ks/vs
        for (int i = tid; i < 64 * 16; i += 256) {
            int r = i >> 4, c = (i & 15) * 4;
            *(float4*)&ks[r * STR + c] = *(const float4*)(kg + (size_t)r * D_ + c);
            *(float4*)&vs[r * STR + c] = *(const float4*)(vg + (size_t)r * D_ + c);
        }
        __syncthreads();

        // S = q @ k^T  (rows ty*4+i, cols tx+16*j)
        float s[4][4];
#pragma unroll
        for (int i = 0; i < 4; i++)
#pragma unroll
            for (int j = 0; j < 4; j++) s[i][j] = 0.f;

#pragma unroll 4
        for (int d = 0; d < 64; d += 4) {
            float4 qv[4], kv[4];
#pragma unroll
            for (int i = 0; i < 4; i++)
                qv[i] = *(const float4*)&qs[(ty * 4 + i) * STR + d];
#pragma unroll
            for (int j = 0; j < 4; j++)
                kv[j] = *(const float4*)&ks[(tx + 16 * j) * STR + d];
#pragma unroll
            for (int i = 0; i < 4; i++)
#pragma unroll
                for (int j = 0; j < 4; j++) {
                    s[i][j] = fmaf(qv[i].x, kv[j].x, s[i][j]);
                    s[i][j] = fmaf(qv[i].y, kv[j].y, s[i][j]);
                    s[i][j] = fmaf(qv[i].z, kv[j].z, s[i][j]);
                    s[i][j] = fmaf(qv[i].w, kv[j].w, s[i][j]);
                }
        }

        // Causal mask on diagonal tile
        if (kt == qt) {
#pragma unroll
            for (int i = 0; i < 4; i++)
#pragma unroll
                for (int j = 0; j < 4; j++)
                    if ((tx + 16 * j) > (ty * 4 + i)) s[i][j] = -1e30f;
        }

        // Online softmax (row reduce across 16 lanes of same ty)
#pragma unroll
        for (int i = 0; i < 4; i++) {
            float mx = fmaxf(fmaxf(s[i][0], s[i][1]), fmaxf(s[i][2], s[i][3]));
#pragma unroll
            for (int off = 8; off >= 1; off >>= 1)
                mx = fmaxf(mx, __shfl_xor_sync(0xffffffffu, mx, off));
            float mn = fmaxf(m[i], mx);
            float f  = __expf(m[i] - mn);
            float rs = 0.f;
#pragma unroll
            for (int j = 0; j < 4; j++) {
                s[i][j] = __expf(s[i][j] - mn);
                rs += s[i][j];
            }
#pragma unroll
            for (int off = 8; off >= 1; off >>= 1)
                rs += __shfl_xor_sync(0xffffffffu, rs, off);
            l[i] = l[i] * f + rs;
            m[i] = mn;
#pragma unroll
            for (int j = 0; j < 4; j++) o[i][j] *= f;
#pragma unroll
            for (int j = 0; j < 4; j++)
                ps[(ty * 4 + i) * STR + tx + 16 * j] = s[i][j];
        }
        __syncthreads();

        // O += P @ V  (O cols tx*4+j)
#pragma unroll 4
        for (int c = 0; c < 64; c += 4) {
            float4 pv[4], vv[4];
#pragma unroll
            for (int i = 0; i < 4; i++)
                pv[i] = *(const float4*)&ps[(ty * 4 + i) * STR + c];
#pragma unroll
            for (int dd = 0; dd < 4; dd++)
                vv[dd] = *(const float4*)&vs[(c + dd) * STR + tx * 4];
#pragma unroll
            for (int i = 0; i < 4; i++) {
                o[i][0] = fmaf(pv[i].x, vv[0].x, o[i][0]);
                o[i][1] = fmaf(pv[i].x, vv[0].y, o[i][1]);
                o[i][2] = fmaf(pv[i].x, vv[0].z, o[i][2]);
                o[i][3] = fmaf(pv[i].x, vv[0].w, o[i][3]);
                o[i][0] = fmaf(pv[i].y, vv[1].x, o[i][0]);
                o[i][1] = fmaf(pv[i].y, vv[1].y, o[i][1]);
                o[i][2] = fmaf(pv[i].y, vv[1].z, o[i][2]);
                o[i][3] = fmaf(pv[i].y, vv[1].w, o[i][3]);
                o[i][0] = fmaf(pv[i].z, vv[2].x, o[i][0]);
                o[i][1] = fmaf(pv[i].z, vv[2].y, o[i][1]);
                o[i][2] = fmaf(pv[i].z, vv[2].z, o[i][2]);
                o[i][3] = fmaf(pv[i].z, vv[2].w, o[i][3]);
                o[i][0] = fmaf(pv[i].w, vv[3].x, o[i][0]);
                o[i][1] = fmaf(pv[i].w, vv[3].y, o[i][1]);
                o[i][2] = fmaf(pv[i].w, vv[3].z, o[i][2]);
                o[i][3] = fmaf(pv[i].w, vv[3].w, o[i][3]);
            }
        }
    }

    // Normalize + write
    float* og = O + (size_t)(b * T_ + qt * 64) * D_ + h * 64;
#pragma unroll
    for (int i = 0; i < 4; i++) {
        float inv = 1.f / l[i];
        float4 r;
        r.x = o[i][0] * inv; r.y = o[i][1] * inv;
        r.z = o[i][2] * inv; r.w = o[i][3] * inv;
        *(float4*)(og + (size_t)(ty * 4 + i) * D_ + tx * 4) = r;
    }
}

// ---------------------------------------------------------------------------
// Launch. Inputs (metadata order):
// 0:x 1:k_cache 2:v_cache 3:mask 4:Wq 5:bq 6:Wk 7:Wv 8:bv 9:Wo 10:bo
// Output: [out | k_cache | v_cache], each B*T*D fp32.
// ---------------------------------------------------------------------------
extern "C" void kernel_launch(void* const* d_in, const int* in_sizes, int n_in,
                              void* d_out, int out_size)
{
    (void)in_sizes; (void)n_in; (void)out_size;
    const float* x   = (const float*)d_in[0];
    const float* Wq  = (const float*)d_in[4];
    const float* bq  = (const float*)d_in[5];
    const float* Wk  = (const float*)d_in[6];
    const float* Wv  = (const float*)d_in[7];
    const float* bvp = (const float*)d_in[8];
    const float* Wo  = (const float*)d_in[9];
    const float* bo  = (const float*)d_in[10];

    float* out = (float*)d_out;
    float* kc  = out + (size_t)MTOT * D_;
    float* vc  = kc  + (size_t)MTOT * D_;

    float *Qs, *WVs;
    cudaGetSymbolAddress((void**)&Qs,  g_Q);
    cudaGetSymbolAddress((void**)&WVs, g_WV);

    dim3 gg(D_ / 128, MTOT / 128);   // (10, 64)
    gemm_bias_kernel<<<gg, 256>>>(x, Wq, bq,      Qs);   // Q
    gemm_bias_kernel<<<gg, 256>>>(x, Wk, nullptr, kc);   // K (no bias)
    gemm_bias_kernel<<<gg, 256>>>(x, Wv, bvp,     vc);   // V

    size_t smem = 4 * 64 * STR * sizeof(float);          // 69,632 B
    cudaFuncSetAttribute(attn_kernel,
                         cudaFuncAttributeMaxDynamicSharedMemorySize,
                         (int)smem);
    dim3 ga(B_ * H_, T_ / 64);       // (160, 16)
    attn_kernel<<<ga, 256, smem>>>(Qs, kc, vc, WVs);

    gemm_bias_kernel<<<gg, 256>>>(WVs, Wo, bo, out);     // output proj
}

// round 4
// speedup vs baseline: 1.7078x; 1.7078x over previous
#include <cuda_runtime.h>
#include <cuda_bf16.h>
#include <cstdint>

#define B_   8
#define T_   1024
#define D_   1280
#define H_   20
#define MTOT (B_ * T_)   // 8192

// ---------------------------------------------------------------------------
// Scratch (device globals; no allocation allowed)
// ---------------------------------------------------------------------------
__device__ float          g_Q [(size_t)MTOT * D_];
__device__ float          g_WV[(size_t)MTOT * D_];
__device__ __nv_bfloat16  g_Xh[(size_t)MTOT * D_];
__device__ __nv_bfloat16  g_Xl[(size_t)MTOT * D_];
__device__ __nv_bfloat16  g_Vh[(size_t)MTOT * D_];   // WV split hi
__device__ __nv_bfloat16  g_Vl[(size_t)MTOT * D_];
__device__ __nv_bfloat16  g_Wth[4 * (size_t)D_ * D_]; // transposed weights hi [N][K]
__device__ __nv_bfloat16  g_Wtl[4 * (size_t)D_ * D_];

// ---------------------------------------------------------------------------
// PTX helpers (sm_103 plain target — NO tcgen05)
// ---------------------------------------------------------------------------
__device__ __forceinline__ uint32_t smem_u32(const void* p) {
    uint32_t a;
    asm("{ .reg .u64 t; cvta.to.shared.u64 t, %1; cvt.u32.u64 %0, t; }"
        : "=r"(a) : "l"(p));
    return a;
}
__device__ __forceinline__ void cpa16(uint32_t dst, const void* src) {
    asm volatile("cp.async.cg.shared.global [%0], [%1], 16;"
                 :: "r"(dst), "l"(src));
}
__device__ __forceinline__ void cpa_commit() {
    asm volatile("cp.async.commit_group;" ::: "memory");
}
__device__ __forceinline__ void cpa_wait1() {
    asm volatile("cp.async.wait_group 1;" ::: "memory");
}
__device__ __forceinline__ void cpa_wait0() {
    asm volatile("cp.async.wait_group 0;" ::: "memory");
}
__device__ __forceinline__ void ldsm_x4(uint32_t* r, uint32_t addr) {
    asm volatile("ldmatrix.sync.aligned.m8n8.x4.shared.b16 {%0,%1,%2,%3}, [%4];"
                 : "=r"(r[0]), "=r"(r[1]), "=r"(r[2]), "=r"(r[3]) : "r"(addr));
}
__device__ __forceinline__ void mma_bf16(float* c, const uint32_t* a, const uint32_t* b) {
    asm volatile(
        "mma.sync.aligned.m16n8k16.row.col.f32.bf16.bf16.f32 "
        "{%0,%1,%2,%3}, {%4,%5,%6,%7}, {%8,%9}, {%0,%1,%2,%3};"
        : "+f"(c[0]), "+f"(c[1]), "+f"(c[2]), "+f"(c[3])
        : "r"(a[0]), "r"(a[1]), "r"(a[2]), "r"(a[3]), "r"(b[0]), "r"(b[1]));
}

// ---------------------------------------------------------------------------
// Prepass 1: fp32 -> bf16 hi/lo split (elementwise)
// ---------------------------------------------------------------------------
__global__ __launch_bounds__(256) void split_kernel(
    const float* __restrict__ src,
    __nv_bfloat16* __restrict__ hi, __nv_bfloat16* __restrict__ lo, int n)
{
    int i = (blockIdx.x * 256 + threadIdx.x) * 4;
    if (i >= n) return;
    float4 v = *(const float4*)(src + i);
    __nv_bfloat16 h0 = __float2bfloat16_rn(v.x);
    __nv_bfloat16 h1 = __float2bfloat16_rn(v.y);
    __nv_bfloat16 h2 = __float2bfloat16_rn(v.z);
    __nv_bfloat16 h3 = __float2bfloat16_rn(v.w);
    __nv_bfloat16 l0 = __float2bfloat16_rn(v.x - __bfloat162float(h0));
    __nv_bfloat16 l1 = __float2bfloat16_rn(v.y - __bfloat162float(h1));
    __nv_bfloat16 l2 = __float2bfloat16_rn(v.z - __bfloat162float(h2));
    __nv_bfloat16 l3 = __float2bfloat16_rn(v.w - __bfloat162float(h3));
    __nv_bfloat162* hp = (__nv_bfloat162*)(hi + i);
    __nv_bfloat162* lp = (__nv_bfloat162*)(lo + i);
    hp[0] = __nv_bfloat162(h0, h1); hp[1] = __nv_bfloat162(h2, h3);
    lp[0] = __nv_bfloat162(l0, l1); lp[1] = __nv_bfloat162(l2, l3);
}

// ---------------------------------------------------------------------------
// Prepass 2: W[k][n] -> Wt_hi/lo[n][k] (fused transpose + split)
// ---------------------------------------------------------------------------
__global__ __launch_bounds__(256) void transpose_split_kernel(
    const float* __restrict__ src,
    __nv_bfloat16* __restrict__ hi, __nv_bfloat16* __restrict__ lo)
{
    __shared__ float t[32][33];
    int bx = blockIdx.x * 32, by = blockIdx.y * 32;
    int x = bx + threadIdx.x;
    int y = by + threadIdx.y;
#pragma unroll
    for (int i = 0; i < 32; i += 8)
        t[threadIdx.y + i][threadIdx.x] = src[(size_t)(y + i) * D_ + x];
    __syncthreads();
    int x2 = by + threadIdx.x;
    int y2 = bx + threadIdx.y;
#pragma unroll
    for (int i = 0; i < 32; i += 8) {
        float v = t[threadIdx.x][threadIdx.y + i];
        __nv_bfloat16 h = __float2bfloat16_rn(v);
        __nv_bfloat16 l = __float2bfloat16_rn(v - __bfloat162float(h));
        hi[(size_t)(y2 + i) * D_ + x2] = h;
        lo[(size_t)(y2 + i) * D_ + x2] = l;
    }
}

// ---------------------------------------------------------------------------
// bf16x3 mma.sync GEMM: C[M,N] = A[M,K] @ Bt[N,K]^T (+bias), fp32 accum.
// 128x128 CTA tile, BK=32, 8 warps (64x32 each), cp.async double buffer.
// smem rows padded to 40 bf16 (80B) -> conflict-free ldmatrix.
// ---------------------------------------------------------------------------
#define ASTR 40                       // bf16 elems per smem row (80 B)
#define SSB  (128 * ASTR * 2)         // bytes per (array, stage) = 10240
#define GEMM_SMEM (8 * SSB)           // 4 arrays x 2 stages = 81920 B

__global__ __launch_bounds__(256, 2) void gemm_mma_kernel(
    const __nv_bfloat16* __restrict__ Ah, const __nv_bfloat16* __restrict__ Al,
    const __nv_bfloat16* __restrict__ Bh, const __nv_bfloat16* __restrict__ Bl,
    const float* __restrict__ bias, float* __restrict__ C)
{
    extern __shared__ char smem[];
    const uint32_t sb = smem_u32(smem);

    const int tid = threadIdx.x;
    const int wid = tid >> 5, lid = tid & 31;
    const int bm = blockIdx.y * 128;
    const int bn = blockIdx.x * 128;
    const int wm = (wid >> 2) * 64;       // warp M offset
    const int wn = (wid & 3) * 32;        // warp N offset

    // cp.async per-thread coords: 2 rows/thread-pair, 2 segs each
    const int lrow  = tid >> 1;           // 0..127
    const int lseg  = (tid & 1) * 16;     // byte offset (0 or 16)

    // ldmatrix per-lane address components
    const int arow = lid & 15;
    const int ak   = (lid >> 4) * 16;     // byte offset within k16
    const int bgrp = lid >> 3;
    const int brow = (lid & 7) + ((bgrp >> 1) << 3);
    const int bk   = (bgrp & 1) * 16;

    float acc[4][4][4];
#pragma unroll
    for (int i = 0; i < 4; i++)
#pragma unroll
        for (int j = 0; j < 4; j++)
#pragma unroll
            for (int k = 0; k < 4; k++) acc[i][j][k] = 0.f;

#define STG_(arr, stage) (sb + ((arr) * 2 + (stage)) * SSB)

#define LOADSTAGE(kb, stage)                                                   \
    {                                                                          \
        size_t ga = (size_t)(bm + lrow) * D_ + (kb) * 32 + lseg / 2;           \
        size_t gb = (size_t)(bn + lrow) * D_ + (kb) * 32 + lseg / 2;           \
        uint32_t so = (uint32_t)(lrow * 80 + lseg);                            \
        cpa16(STG_(0, stage) + so,      Ah + ga);                              \
        cpa16(STG_(0, stage) + so + 32, Ah + ga + 16);                         \
        cpa16(STG_(1, stage) + so,      Al + ga);                              \
        cpa16(STG_(1, stage) + so + 32, Al + ga + 16);                         \
        cpa16(STG_(2, stage) + so,      Bh + gb);                              \
        cpa16(STG_(2, stage) + so + 32, Bh + gb + 16);                         \
        cpa16(STG_(3, stage) + so,      Bl + gb);                              \
        cpa16(STG_(3, stage) + so + 32, Bl + gb + 16);                         \
        cpa_commit();                                                          \
    }

    LOADSTAGE(0, 0);

    for (int kb = 0; kb < 40; kb++) {
        const int st = kb & 1;
        if (kb < 39) { LOADSTAGE(kb + 1, st ^ 1); cpa_wait1(); }
        else         { cpa_wait0(); }
        __syncthreads();

        const uint32_t aB  = STG_(0, st), alB = STG_(1, st);
        const uint32_t bB  = STG_(2, st), blB = STG_(3, st);
#pragma unroll
        for (int kk = 0; kk < 2; kk++) {
            const uint32_t ko = kk * 32;
            uint32_t bh[8], bl[8];
            ldsm_x4(&bh[0], bB  + (uint32_t)(wn + brow)      * 80 + bk + ko);
            ldsm_x4(&bh[4], bB  + (uint32_t)(wn + 16 + brow) * 80 + bk + ko);
            ldsm_x4(&bl[0], blB + (uint32_t)(wn + brow)      * 80 + bk + ko);
            ldsm_x4(&bl[4], blB + (uint32_t)(wn + 16 + brow) * 80 + bk + ko);
#pragma unroll
            for (int mt = 0; mt < 4; mt++) {
                uint32_t ah[4], alr[4];
                ldsm_x4(ah,  aB  + (uint32_t)(wm + mt * 16 + arow) * 80 + ak + ko);
                ldsm_x4(alr, alB + (uint32_t)(wm + mt * 16 + arow) * 80 + ak + ko);
#pragma unroll
                for (int nt = 0; nt < 4; nt++) {
                    mma_bf16(acc[mt][nt], ah,  &bh[nt * 2]);
                    mma_bf16(acc[mt][nt], ah,  &bl[nt * 2]);
                    mma_bf16(acc[mt][nt], alr, &bh[nt * 2]);
                }
            }
        }
        __syncthreads();
    }

    // Epilogue: direct float2 stores with bias
    const int g = lid >> 2, tg = lid & 3;
#pragma unroll
    for (int mt = 0; mt < 4; mt++) {
#pragma unroll
        for (int nt = 0; nt < 4; nt++) {
            int row = bm + wm + mt * 16 + g;
            int col = bn + wn + nt * 8 + tg * 2;
            float b0 = 0.f, b1 = 0.f;
            if (bias) { b0 = bias[col]; b1 = bias[col + 1]; }
            float2 v0, v1;
            v0.x = acc[mt][nt][0] + b0; v0.y = acc[mt][nt][1] + b1;
            v1.x = acc[mt][nt][2] + b0; v1.y = acc[mt][nt][3] + b1;
            *(float2*)(C + (size_t)row * D_ + col)       = v0;
            *(float2*)(C + (size_t)(row + 8) * D_ + col) = v1;
        }
    }
}

// ---------------------------------------------------------------------------
// Causal flash attention, fp32 (unchanged; next-round target)
// ---------------------------------------------------------------------------
#define STR 68

__global__ __launch_bounds__(256) void attn_kernel(
    const float* __restrict__ Q, const float* __restrict__ Kc,
    const float* __restrict__ Vc, float* __restrict__ O)
{
    extern __shared__ float smf[];
    float* qs = smf;
    float* ks = smf + 64 * STR;
    float* vs = smf + 2 * 64 * STR;
    float* ps = smf + 3 * 64 * STR;

    const int tid = threadIdx.x;
    const int tx = tid & 15;
    const int ty = tid >> 4;
    const int bh = blockIdx.x;
    const int b  = bh / H_;
    const int h  = bh % H_;
    const int qt = blockIdx.y;
    const float scale = 0.125f;

    const float* qg = Q + (size_t)(b * T_ + qt * 64) * D_ + h * 64;
    for (int i = tid; i < 64 * 16; i += 256) {
        int r = i >> 4, c = (i & 15) * 4;
        float4 v = *(const float4*)(qg + (size_t)r * D_ + c);
        qs[r * STR + c + 0] = v.x * scale;
        qs[r * STR + c + 1] = v.y * scale;
        qs[r * STR + c + 2] = v.z * scale;
        qs[r * STR + c + 3] = v.w * scale;
    }

    float m[4], l[4], o[4][4];
#pragma unroll
    for (int i = 0; i < 4; i++) {
        m[i] = -1e30f; l[i] = 0.f;
#pragma unroll
        for (int j = 0; j < 4; j++) o[i][j] = 0.f;
    }

    for (int kt = 0; kt <= qt; kt++) {
        const float* kg = Kc + (size_t)(b * T_ + kt * 64) * D_ + h * 64;
        const float* vg = Vc + (size_t)(b * T_ + kt * 64) * D_ + h * 64;
        __syncthreads();
        for (int i = tid; i < 64 * 16; i += 256) {
            int r = i >> 4, c = (i & 15) * 4;
            *(float4*)&ks[r * STR + c] = *(const float4*)(kg + (size_t)r * D_ + c);
            *(float4*)&vs[r * STR + c] = *(const float4*)(vg + (size_t)r * D_ + c);
        }
        __syncthreads();

        float s[4][4];
#pragma unroll
        for (int i = 0; i < 4; i++)
#pragma unroll
            for (int j = 0; j < 4; j++) s[i][j] = 0.f;

#pragma unroll 4
        for (int d = 0; d < 64; d += 4) {
            float4 qv[4], kv[4];
#pragma unroll
            for (int i = 0; i < 4; i++)
                qv[i] = *(const float4*)&qs[(ty * 4 + i) * STR + d];
#pragma unroll
            for (int j = 0; j < 4; j++)
                kv[j] = *(const float4*)&ks[(tx + 16 * j) * STR + d];
#pragma unroll
            for (int i = 0; i < 4; i++)
#pragma unroll
                for (int j = 0; j < 4; j++) {
                    s[i][j] = fmaf(qv[i].x, kv[j].x, s[i][j]);
                    s[i][j] = fmaf(qv[i].y, kv[j].y, s[i][j]);
                    s[i][j] = fmaf(qv[i].z, kv[j].z, s[i][j]);
                    s[i][j] = fmaf(qv[i].w, kv[j].w, s[i][j]);
                }
        }

        if (kt == qt) {
#pragma unroll
            for (int i = 0; i < 4; i++)
#pragma unroll
                for (int j = 0; j < 4; j++)
                    if ((tx + 16 * j) > (ty * 4 + i)) s[i][j] = -1e30f;
        }

#pragma unroll
        for (int i = 0; i < 4; i++) {
            float mx = fmaxf(fmaxf(s[i][0], s[i][1]), fmaxf(s[i][2], s[i][3]));
#pragma unroll
            for (int off = 8; off >= 1; off >>= 1)
                mx = fmaxf(mx, __shfl_xor_sync(0xffffffffu, mx, off));
            float mn = fmaxf(m[i], mx);
            float f  = __expf(m[i] - mn);
            float rs = 0.f;
#pragma unroll
            for (int j = 0; j < 4; j++) {
                s[i][j] = __expf(s[i][j] - mn);
                rs += s[i][j];
            }
#pragma unroll
            for (int off = 8; off >= 1; off >>= 1)
                rs += __shfl_xor_sync(0xffffffffu, rs, off);
            l[i] = l[i] * f + rs;
            m[i] = mn;
#pragma unroll
            for (int j = 0; j < 4; j++) o[i][j] *= f;
#pragma unroll
            for (int j = 0; j < 4; j++)
                ps[(ty * 4 + i) * STR + tx + 16 * j] = s[i][j];
        }
        __syncthreads();

#pragma unroll 4
        for (int c = 0; c < 64; c += 4) {
            float4 pv[4], vv[4];
#pragma unroll
            for (int i = 0; i < 4; i++)
                pv[i] = *(const float4*)&ps[(ty * 4 + i) * STR + c];
#pragma unroll
            for (int dd = 0; dd < 4; dd++)
                vv[dd] = *(const float4*)&vs[(c + dd) * STR + tx * 4];
#pragma unroll
            for (int i = 0; i < 4; i++) {
                o[i][0] = fmaf(pv[i].x, vv[0].x, o[i][0]);
                o[i][1] = fmaf(pv[i].x, vv[0].y, o[i][1]);
                o[i][2] = fmaf(pv[i].x, vv[0].z, o[i][2]);
                o[i][3] = fmaf(pv[i].x, vv[0].w, o[i][3]);
                o[i][0] = fmaf(pv[i].y, vv[1].x, o[i][0]);
                o[i][1] = fmaf(pv[i].y, vv[1].y, o[i][1]);
                o[i][2] = fmaf(pv[i].y, vv[1].z, o[i][2]);
                o[i][3] = fmaf(pv[i].y, vv[1].w, o[i][3]);
                o[i][0] = fmaf(pv[i].z, vv[2].x, o[i][0]);
                o[i][1] = fmaf(pv[i].z, vv[2].y, o[i][1]);
                o[i][2] = fmaf(pv[i].z, vv[2].z, o[i][2]);
                o[i][3] = fmaf(pv[i].z, vv[2].w, o[i][3]);
                o[i][0] = fmaf(pv[i].w, vv[3].x, o[i][0]);
                o[i][1] = fmaf(pv[i].w, vv[3].y, o[i][1]);
                o[i][2] = fmaf(pv[i].w, vv[3].z, o[i][2]);
                o[i][3] = fmaf(pv[i].w, vv[3].w, o[i][3]);
            }
        }
    }

    float* og = O + (size_t)(b * T_ + qt * 64) * D_ + h * 64;
#pragma unroll
    for (int i = 0; i < 4; i++) {
        float inv = 1.f / l[i];
        float4 r;
        r.x = o[i][0] * inv; r.y = o[i][1] * inv;
        r.z = o[i][2] * inv; r.w = o[i][3] * inv;
        *(float4*)(og + (size_t)(ty * 4 + i) * D_ + tx * 4) = r;
    }
}

// ---------------------------------------------------------------------------
// Launch. Inputs: 0:x 1:k_cache 2:v_cache 3:mask 4:Wq 5:bq 6:Wk 7:Wv 8:bv 9:Wo 10:bo
// Output: [out | k_cache | v_cache]
// ---------------------------------------------------------------------------
extern "C" void kernel_launch(void* const* d_in, const int* in_sizes, int n_in,
                              void* d_out, int out_size)
{
    (void)in_sizes; (void)n_in; (void)out_size;
    const float* x   = (const float*)d_in[0];
    const float* Wq  = (const float*)d_in[4];
    const float* bq  = (const float*)d_in[5];
    const float* Wk  = (const float*)d_in[6];
    const float* Wv  = (const float*)d_in[7];
    const float* bvp = (const float*)d_in[8];
    const float* Wo  = (const float*)d_in[9];
    const float* bo  = (const float*)d_in[10];

    float* out = (float*)d_out;
    float* kc  = out + (size_t)MTOT * D_;
    float* vc  = kc  + (size_t)MTOT * D_;

    float *Qs, *WVs;
    __nv_bfloat16 *Xh, *Xl, *Vh, *Vl, *Wth, *Wtl;
    cudaGetSymbolAddress((void**)&Qs,  g_Q);
    cudaGetSymbolAddress((void**)&WVs, g_WV);
    cudaGetSymbolAddress((void**)&Xh,  g_Xh);
    cudaGetSymbolAddress((void**)&Xl,  g_Xl);
    cudaGetSymbolAddress((void**)&Vh,  g_Vh);
    cudaGetSymbolAddress((void**)&Vl,  g_Vl);
    cudaGetSymbolAddress((void**)&Wth, g_Wth);
    cudaGetSymbolAddress((void**)&Wtl, g_Wtl);

    const size_t WSZ = (size_t)D_ * D_;
    const int NX = MTOT * D_;

    // Prepasses: weight transpose+split, x split
    dim3 tg(D_ / 32, D_ / 32), tb(32, 8);
    transpose_split_kernel<<<tg, tb>>>(Wq, Wth + 0 * WSZ, Wtl + 0 * WSZ);
    transpose_split_kernel<<<tg, tb>>>(Wk, Wth + 1 * WSZ, Wtl + 1 * WSZ);
    transpose_split_kernel<<<tg, tb>>>(Wv, Wth + 2 * WSZ, Wtl + 2 * WSZ);
    transpose_split_kernel<<<tg, tb>>>(Wo, Wth + 3 * WSZ, Wtl + 3 * WSZ);
    split_kernel<<<NX / (256 * 4), 256>>>(x, Xh, Xl, NX);

    cudaFuncSetAttribute(gemm_mma_kernel,
                         cudaFuncAttributeMaxDynamicSharedMemorySize, GEMM_SMEM);
    dim3 gg(D_ / 128, MTOT / 128);   // (10, 64)
    gemm_mma_kernel<<<gg, 256, GEMM_SMEM>>>(Xh, Xl, Wth + 0 * WSZ, Wtl + 0 * WSZ, bq,      Qs);
    gemm_mma_kernel<<<gg, 256, GEMM_SMEM>>>(Xh, Xl, Wth + 1 * WSZ, Wtl + 1 * WSZ, nullptr, kc);
    gemm_mma_kernel<<<gg, 256, GEMM_SMEM>>>(Xh, Xl, Wth + 2 * WSZ, Wtl + 2 * WSZ, bvp,     vc);

    size_t asmem = 4 * 64 * STR * sizeof(float);
    cudaFuncSetAttribute(attn_kernel,
                         cudaFuncAttributeMaxDynamicSharedMemorySize, (int)asmem);
    dim3 ga(B_ * H_, T_ / 64);
    attn_kernel<<<ga, 256, asmem>>>(Qs, kc, vc, WVs);

    split_kernel<<<NX / (256 * 4), 256>>>(WVs, Vh, Vl, NX);
    gemm_mma_kernel<<<gg, 256, GEMM_SMEM>>>(Vh, Vl, Wth + 3 * WSZ, Wtl + 3 * WSZ, bo, out);
}

// round 6
// speedup vs baseline: 2.1291x; 1.2467x over previous
#include <cuda_runtime.h>
#include <cuda_bf16.h>
#include <cstdint>

#define B_   8
#define T_   1024
#define D_   1280
#define H_   20
#define MTOT (B_ * T_)   // 8192

// ---------------------------------------------------------------------------
// Scratch (device globals; no allocation allowed)
// ---------------------------------------------------------------------------
__device__ __nv_bfloat16  g_Xh[(size_t)MTOT * D_];
__device__ __nv_bfloat16  g_Xl[(size_t)MTOT * D_];
__device__ __nv_bfloat16  g_Qh[(size_t)MTOT * D_];
__device__ __nv_bfloat16  g_Ql[(size_t)MTOT * D_];
__device__ __nv_bfloat16  g_Kh[(size_t)MTOT * D_];
__device__ __nv_bfloat16  g_Kl[(size_t)MTOT * D_];
__device__ __nv_bfloat16  g_Vh[(size_t)MTOT * D_];
__device__ __nv_bfloat16  g_Vl[(size_t)MTOT * D_];
__device__ __nv_bfloat16  g_Ah[(size_t)MTOT * D_];   // attention out (WV) hi
__device__ __nv_bfloat16  g_Al[(size_t)MTOT * D_];
__device__ __nv_bfloat16  g_Wth[4 * (size_t)D_ * D_]; // transposed weights hi [N][K]
__device__ __nv_bfloat16  g_Wtl[4 * (size_t)D_ * D_];

// ---------------------------------------------------------------------------
// PTX helpers (plain sm_103 target — NO tcgen05)
// ---------------------------------------------------------------------------
__device__ __forceinline__ uint32_t smem_u32(const void* p) {
    uint32_t a;
    asm("{ .reg .u64 t; cvta.to.shared.u64 t, %1; cvt.u32.u64 %0, t; }"
        : "=r"(a) : "l"(p));
    return a;
}
__device__ __forceinline__ void cpa16(uint32_t dst, const void* src) {
    asm volatile("cp.async.cg.shared.global [%0], [%1], 16;"
                 :: "r"(dst), "l"(src));
}
__device__ __forceinline__ void cpa_commit() {
    asm volatile("cp.async.commit_group;" ::: "memory");
}
__device__ __forceinline__ void cpa_wait0() { asm volatile("cp.async.wait_group 0;" ::: "memory"); }
__device__ __forceinline__ void cpa_wait1() { asm volatile("cp.async.wait_group 1;" ::: "memory"); }
__device__ __forceinline__ void cpa_wait2() { asm volatile("cp.async.wait_group 2;" ::: "memory"); }
__device__ __forceinline__ void ldsm_x4(uint32_t* r, uint32_t addr) {
    asm volatile("ldmatrix.sync.aligned.m8n8.x4.shared.b16 {%0,%1,%2,%3}, [%4];"
                 : "=r"(r[0]), "=r"(r[1]), "=r"(r[2]), "=r"(r[3]) : "r"(addr));
}
__device__ __forceinline__ void ldsm_x4t(uint32_t* r, uint32_t addr) {
    asm volatile("ldmatrix.sync.aligned.m8n8.x4.trans.shared.b16 {%0,%1,%2,%3}, [%4];"
                 : "=r"(r[0]), "=r"(r[1]), "=r"(r[2]), "=r"(r[3]) : "r"(addr));
}
__device__ __forceinline__ void mma_bf16(float* c, const uint32_t* a, const uint32_t* b) {
    asm volatile(
        "mma.sync.aligned.m16n8k16.row.col.f32.bf16.bf16.f32 "
        "{%0,%1,%2,%3}, {%4,%5,%6,%7}, {%8,%9}, {%0,%1,%2,%3};"
        : "+f"(c[0]), "+f"(c[1]), "+f"(c[2]), "+f"(c[3])
        : "r"(a[0]), "r"(a[1]), "r"(a[2]), "r"(a[3]), "r"(b[0]), "r"(b[1]));
}
__device__ __forceinline__ uint32_t pack_bf2(float x, float y) {
    __nv_bfloat162 t = __floats2bfloat162_rn(x, y);   // .x = x (low half)
    return *(uint32_t*)&t;
}

// ---------------------------------------------------------------------------
// Prepass 1: fp32 -> bf16 hi/lo split (elementwise)
// ---------------------------------------------------------------------------
__global__ __launch_bounds__(256) void split_kernel(
    const float* __restrict__ src,
    __nv_bfloat16* __restrict__ hi, __nv_bfloat16* __restrict__ lo, int n)
{
    int i = (blockIdx.x * 256 + threadIdx.x) * 4;
    if (i >= n) return;
    float4 v = *(const float4*)(src + i);
    __nv_bfloat16 h0 = __float2bfloat16_rn(v.x);
    __nv_bfloat16 h1 = __float2bfloat16_rn(v.y);
    __nv_bfloat16 h2 = __float2bfloat16_rn(v.z);
    __nv_bfloat16 h3 = __float2bfloat16_rn(v.w);
    __nv_bfloat16 l0 = __float2bfloat16_rn(v.x - __bfloat162float(h0));
    __nv_bfloat16 l1 = __float2bfloat16_rn(v.y - __bfloat162float(h1));
    __nv_bfloat16 l2 = __float2bfloat16_rn(v.z - __bfloat162float(h2));
    __nv_bfloat16 l3 = __float2bfloat16_rn(v.w - __bfloat162float(h3));
    __nv_bfloat162* hp = (__nv_bfloat162*)(hi + i);
    __nv_bfloat162* lp = (__nv_bfloat162*)(lo + i);
    hp[0] = __nv_bfloat162(h0, h1); hp[1] = __nv_bfloat162(h2, h3);
    lp[0] = __nv_bfloat162(l0, l1); lp[1] = __nv_bfloat162(l2, l3);
}

// ---------------------------------------------------------------------------
// Prepass 2: W[k][n] -> Wt_hi/lo[n][k] (fused transpose + split)
// ---------------------------------------------------------------------------
__global__ __launch_bounds__(256) void transpose_split_kernel(
    const float* __restrict__ src,
    __nv_bfloat16* __restrict__ hi, __nv_bfloat16* __restrict__ lo)
{
    __shared__ float t[32][33];
    int bx = blockIdx.x * 32, by = blockIdx.y * 32;
    int x = bx + threadIdx.x;
    int y = by + threadIdx.y;
#pragma unroll
    for (int i = 0; i < 32; i += 8)
        t[threadIdx.y + i][threadIdx.x] = src[(size_t)(y + i) * D_ + x];
    __syncthreads();
    int x2 = by + threadIdx.x;
    int y2 = bx + threadIdx.y;
#pragma unroll
    for (int i = 0; i < 32; i += 8) {
        float v = t[threadIdx.x][threadIdx.y + i];
        __nv_bfloat16 h = __float2bfloat16_rn(v);
        __nv_bfloat16 l = __float2bfloat16_rn(v - __bfloat162float(h));
        hi[(size_t)(y2 + i) * D_ + x2] = h;
        lo[(size_t)(y2 + i) * D_ + x2] = l;
    }
}

// ---------------------------------------------------------------------------
// bf16x3 mma.sync GEMM: C[M,N] = A[M,K] @ Bt[N,K]^T (+bias), fp32 accum.
// Optional fp32 output C and/or bf16 hi/lo split outputs Oh/Ol.
// ---------------------------------------------------------------------------
#define ASTR 40                       // bf16 elems per smem row (80 B)
#define SSB  (128 * ASTR * 2)         // bytes per (array, stage) = 10240
#define GEMM_SMEM (8 * SSB)           // 4 arrays x 2 stages = 81920 B

__global__ __launch_bounds__(256, 2) void gemm_mma_kernel(
    const __nv_bfloat16* __restrict__ Ah, const __nv_bfloat16* __restrict__ Al,
    const __nv_bfloat16* __restrict__ Bh, const __nv_bfloat16* __restrict__ Bl,
    const float* __restrict__ bias, float* __restrict__ C,
    __nv_bfloat16* __restrict__ Oh, __nv_bfloat16* __restrict__ Ol)
{
    extern __shared__ char smem[];
    const uint32_t sb = smem_u32(smem);

    const int tid = threadIdx.x;
    const int wid = tid >> 5, lid = tid & 31;
    const int bm = blockIdx.y * 128;
    const int bn = blockIdx.x * 128;
    const int wm = (wid >> 2) * 64;
    const int wn = (wid & 3) * 32;

    const int lrow  = tid >> 1;
    const int lseg  = (tid & 1) * 16;

    const int arow = lid & 15;
    const int ak   = (lid >> 4) * 16;
    const int bgrp = lid >> 3;
    const int brow = (lid & 7) + ((bgrp >> 1) << 3);
    const int bk   = (bgrp & 1) * 16;

    float acc[4][4][4];
#pragma unroll
    for (int i = 0; i < 4; i++)
#pragma unroll
        for (int j = 0; j < 4; j++)
#pragma unroll
            for (int k = 0; k < 4; k++) acc[i][j][k] = 0.f;

#define STG_(arr, stage) (sb + ((arr) * 2 + (stage)) * SSB)

#define LOADSTAGE(kb, stage)                                                   \
    {                                                                          \
        size_t ga = (size_t)(bm + lrow) * D_ + (kb) * 32 + lseg / 2;           \
        size_t gb = (size_t)(bn + lrow) * D_ + (kb) * 32 + lseg / 2;           \
        uint32_t so = (uint32_t)(lrow * 80 + lseg);                            \
        cpa16(STG_(0, stage) + so,      Ah + ga);                              \
        cpa16(STG_(0, stage) + so + 32, Ah + ga + 16);                         \
        cpa16(STG_(1, stage) + so,      Al + ga);                              \
        cpa16(STG_(1, stage) + so + 32, Al + ga + 16);                         \
        cpa16(STG_(2, stage) + so,      Bh + gb);                              \
        cpa16(STG_(2, stage) + so + 32, Bh + gb + 16);                         \
        cpa16(STG_(3, stage) + so,      Bl + gb);                              \
        cpa16(STG_(3, stage) + so + 32, Bl + gb + 16);                         \
        cpa_commit();                                                          \
    }

    LOADSTAGE(0, 0);

    for (int kb = 0; kb < 40; kb++) {
        const int st = kb & 1;
        if (kb < 39) { LOADSTAGE(kb + 1, st ^ 1); cpa_wait1(); }
        else         { cpa_wait0(); }
        __syncthreads();

        const uint32_t aB  = STG_(0, st), alB = STG_(1, st);
        const uint32_t bB  = STG_(2, st), blB = STG_(3, st);
#pragma unroll
        for (int kk = 0; kk < 2; kk++) {
            const uint32_t ko = kk * 32;
            uint32_t bh[8], bl[8];
            ldsm_x4(&bh[0], bB  + (uint32_t)(wn + brow)      * 80 + bk + ko);
            ldsm_x4(&bh[4], bB  + (uint32_t)(wn + 16 + brow) * 80 + bk + ko);
            ldsm_x4(&bl[0], blB + (uint32_t)(wn + brow)      * 80 + bk + ko);
            ldsm_x4(&bl[4], blB + (uint32_t)(wn + 16 + brow) * 80 + bk + ko);
#pragma unroll
            for (int mt = 0; mt < 4; mt++) {
                uint32_t ah[4], alr[4];
                ldsm_x4(ah,  aB  + (uint32_t)(wm + mt * 16 + arow) * 80 + ak + ko);
                ldsm_x4(alr, alB + (uint32_t)(wm + mt * 16 + arow) * 80 + ak + ko);
#pragma unroll
                for (int nt = 0; nt < 4; nt++) {
                    mma_bf16(acc[mt][nt], ah,  &bh[nt * 2]);
                    mma_bf16(acc[mt][nt], ah,  &bl[nt * 2]);
                    mma_bf16(acc[mt][nt], alr, &bh[nt * 2]);
                }
            }
        }
        __syncthreads();
    }

    // Epilogue
    const int g = lid >> 2, tg = lid & 3;
#pragma unroll
    for (int mt = 0; mt < 4; mt++) {
#pragma unroll
        for (int nt = 0; nt < 4; nt++) {
            int row = bm + wm + mt * 16 + g;
            int col = bn + wn + nt * 8 + tg * 2;
            float b0 = 0.f, b1 = 0.f;
            if (bias) { b0 = bias[col]; b1 = bias[col + 1]; }
            float v00 = acc[mt][nt][0] + b0, v01 = acc[mt][nt][1] + b1;
            float v10 = acc[mt][nt][2] + b0, v11 = acc[mt][nt][3] + b1;
            if (C) {
                *(float2*)(C + (size_t)row * D_ + col)       = make_float2(v00, v01);
                *(float2*)(C + (size_t)(row + 8) * D_ + col) = make_float2(v10, v11);
            }
            if (Oh) {
                __nv_bfloat16 h00 = __float2bfloat16_rn(v00);
                __nv_bfloat16 h01 = __float2bfloat16_rn(v01);
                __nv_bfloat16 h10 = __float2bfloat16_rn(v10);
                __nv_bfloat16 h11 = __float2bfloat16_rn(v11);
                *(__nv_bfloat162*)(Oh + (size_t)row * D_ + col) = __nv_bfloat162(h00, h01);
                *(__nv_bfloat162*)(Oh + (size_t)(row + 8) * D_ + col) = __nv_bfloat162(h10, h11);
                __nv_bfloat16 l00 = __float2bfloat16_rn(v00 - __bfloat162float(h00));
                __nv_bfloat16 l01 = __float2bfloat16_rn(v01 - __bfloat162float(h01));
                __nv_bfloat16 l10 = __float2bfloat16_rn(v10 - __bfloat162float(h10));
                __nv_bfloat16 l11 = __float2bfloat16_rn(v11 - __bfloat162float(h11));
                *(__nv_bfloat162*)(Ol + (size_t)row * D_ + col) = __nv_bfloat162(l00, l01);
                *(__nv_bfloat162*)(Ol + (size_t)(row + 8) * D_ + col) = __nv_bfloat162(l10, l11);
            }
        }
    }
}

// ---------------------------------------------------------------------------
// Causal flash attention via mma.sync (bf16 split precision).
// CTA: 128 q-rows of one (b,h); 8 warps x 16 rows. kv tiles of 64 rows.
// 3-stage cp.async pipeline. smem row stride = 72 bf16 (144 B).
// Writes attention output directly as bf16 hi/lo (input to O GEMM).
// ---------------------------------------------------------------------------
#define AT_QH 0
#define AT_QL 18432
#define AT_KH(st) (36864  + (st) * 9216)
#define AT_KL(st) (64512  + (st) * 9216)
#define AT_VH(st) (92160  + (st) * 9216)
#define AT_VL(st) (119808 + (st) * 9216)
#define ATTN_SMEM 147456

__global__ __launch_bounds__(256, 1) void attn_mma_kernel(
    const __nv_bfloat16* __restrict__ Qh, const __nv_bfloat16* __restrict__ Ql,
    const __nv_bfloat16* __restrict__ Kh, const __nv_bfloat16* __restrict__ Kl,
    const __nv_bfloat16* __restrict__ Vh, const __nv_bfloat16* __restrict__ Vl,
    __nv_bfloat16* __restrict__ Oh, __nv_bfloat16* __restrict__ Ol)
{
    extern __shared__ char smem[];
    const uint32_t sb = smem_u32(smem);

    const int tid = threadIdx.x;
    const int wid = tid >> 5, lid = tid & 31;
    const int bh = blockIdx.x;
    const int b  = bh / H_;
    const int h  = bh % H_;
    const int qb = blockIdx.y;
    const int nkt = 2 * qb + 2;              // kv tiles

    const int g  = lid >> 2, tg = lid & 3;
    const int wr = wid * 16;                 // warp row offset within CTA
    const int qrow0 = qb * 128 + wr;         // global q row base of warp

    // ldmatrix lane address components
    const int arow = lid & 15;
    const int ak   = (lid >> 4) * 16;
    const int bgrp = lid >> 3;
    const int brow = (lid & 7) + ((bgrp >> 1) << 3);
    const int bk   = (bgrp & 1) * 16;
    const int vrow = (lid & 7) + ((bgrp & 1) << 3);   // trans: m0 rows k0-7, m1 k8-15
    const int vck  = (lid >> 4) * 16;                 // m2/m3 at +16B cols

    // ---- prologue loads: Q (hi/lo) and kv stage 0 (+1) -------------------
    {
        const size_t qgbase = (size_t)(b * T_ + qb * 128) * D_ + h * 64;
#pragma unroll
        for (int i = 0; i < 4; i++) {
            int id = tid + i * 256;            // 0..1023
            int r = id >> 3, e = (id & 7) * 8; // elem offset
            uint32_t so = (uint32_t)(r * 144 + e * 2);
            cpa16(sb + AT_QH + so, Qh + qgbase + (size_t)r * D_ + e);
            cpa16(sb + AT_QL + so, Ql + qgbase + (size_t)r * D_ + e);
        }
    }
#define LOADKV(kt, st)                                                         \
    {                                                                          \
        const size_t kvb = (size_t)(b * T_ + (kt) * 64) * D_ + h * 64;         \
        _Pragma("unroll")                                                      \
        for (int i = 0; i < 2; i++) {                                          \
            int id = tid + i * 256;                                            \
            int r = id >> 3, e = (id & 7) * 8;                                 \
            uint32_t so = (uint32_t)(r * 144 + e * 2);                         \
            size_t go = kvb + (size_t)r * D_ + e;                              \
            cpa16(sb + AT_KH(st) + so, Kh + go);                               \
            cpa16(sb + AT_KL(st) + so, Kl + go);                               \
            cpa16(sb + AT_VH(st) + so, Vh + go);                               \
            cpa16(sb + AT_VL(st) + so, Vl + go);                               \
        }                                                                      \
        cpa_commit();                                                          \
    }
    LOADKV(0, 0);                 // group 0 (includes Q loads)
    if (nkt > 1) LOADKV(1, 1);    // group 1

    float m0 = -1e30f, m1 = -1e30f, l0 = 0.f, l1 = 0.f;
    float o[8][4];
#pragma unroll
    for (int j = 0; j < 8; j++)
#pragma unroll
        for (int e = 0; e < 4; e++) o[j][e] = 0.f;

    for (int kt = 0; kt < nkt; kt++) {
        const int st = kt % 3;
        if (kt + 2 < nkt) { LOADKV(kt + 2, (kt + 2) % 3); cpa_wait2(); }
        else if (kt + 1 < nkt) cpa_wait1();
        else cpa_wait0();
        __syncthreads();

        if (kt * 64 <= qrow0 + 15) {
            // ---- S = Q K^T ----
            float s[8][4];
#pragma unroll
            for (int j = 0; j < 8; j++)
#pragma unroll
                for (int e = 0; e < 4; e++) s[j][e] = 0.f;

#pragma unroll
            for (int kc = 0; kc < 4; kc++) {
                uint32_t ah[4], al[4];
                ldsm_x4(ah, sb + AT_QH + (uint32_t)(wr + arow) * 144 + kc * 32 + ak);
                ldsm_x4(al, sb + AT_QL + (uint32_t)(wr + arow) * 144 + kc * 32 + ak);
#pragma unroll
                for (int np = 0; np < 4; np++) {
                    uint32_t kbh[4], kbl[4];
                    ldsm_x4(kbh, sb + AT_KH(st) + (uint32_t)(np * 16 + brow) * 144 + kc * 32 + bk);
                    ldsm_x4(kbl, sb + AT_KL(st) + (uint32_t)(np * 16 + brow) * 144 + kc * 32 + bk);
                    mma_bf16(s[np * 2],     ah, &kbh[0]);
                    mma_bf16(s[np * 2],     ah, &kbl[0]);
                    mma_bf16(s[np * 2],     al, &kbh[0]);
                    mma_bf16(s[np * 2 + 1], ah, &kbh[2]);
                    mma_bf16(s[np * 2 + 1], ah, &kbl[2]);
                    mma_bf16(s[np * 2 + 1], al, &kbh[2]);
                }
            }

            // ---- scale + causal mask ----
            // total score scale = (DH^-0.25)^2 = DH^-0.5 = 1/8  (R5 bug: was 1/64)
            const int r0 = qrow0 + g, r1 = r0 + 8;
#pragma unroll
            for (int j = 0; j < 8; j++) {
                int c0 = kt * 64 + j * 8 + 2 * tg;
                s[j][0] = (c0     <= r0) ? s[j][0] * 0.125f : -1e30f;
                s[j][1] = (c0 + 1 <= r0) ? s[j][1] * 0.125f : -1e30f;
                s[j][2] = (c0     <= r1) ? s[j][2] * 0.125f : -1e30f;
                s[j][3] = (c0 + 1 <= r1) ? s[j][3] * 0.125f : -1e30f;
            }

            // ---- online softmax (rows r0: e0/e1, r1: e2/e3) ----
            float mx0 = -1e30f, mx1 = -1e30f;
#pragma unroll
            for (int j = 0; j < 8; j++) {
                mx0 = fmaxf(mx0, fmaxf(s[j][0], s[j][1]));
                mx1 = fmaxf(mx1, fmaxf(s[j][2], s[j][3]));
            }
            mx0 = fmaxf(mx0, __shfl_xor_sync(0xffffffffu, mx0, 1));
            mx0 = fmaxf(mx0, __shfl_xor_sync(0xffffffffu, mx0, 2));
            mx1 = fmaxf(mx1, __shfl_xor_sync(0xffffffffu, mx1, 1));
            mx1 = fmaxf(mx1, __shfl_xor_sync(0xffffffffu, mx1, 2));
            float mn0 = fmaxf(m0, mx0), mn1 = fmaxf(m1, mx1);
            float f0 = __expf(m0 - mn0), f1 = __expf(m1 - mn1);
            m0 = mn0; m1 = mn1;
            float rs0 = 0.f, rs1 = 0.f;
#pragma unroll
            for (int j = 0; j < 8; j++) {
                s[j][0] = __expf(s[j][0] - mn0);
                s[j][1] = __expf(s[j][1] - mn0);
                s[j][2] = __expf(s[j][2] - mn1);
                s[j][3] = __expf(s[j][3] - mn1);
                rs0 += s[j][0] + s[j][1];
                rs1 += s[j][2] + s[j][3];
            }
            rs0 += __shfl_xor_sync(0xffffffffu, rs0, 1);
            rs0 += __shfl_xor_sync(0xffffffffu, rs0, 2);
            rs1 += __shfl_xor_sync(0xffffffffu, rs1, 1);
            rs1 += __shfl_xor_sync(0xffffffffu, rs1, 2);
            l0 = l0 * f0 + rs0;
            l1 = l1 * f1 + rs1;
#pragma unroll
            for (int j = 0; j < 8; j++) {
                o[j][0] *= f0; o[j][1] *= f0;
                o[j][2] *= f1; o[j][3] *= f1;
            }

            // ---- O += P V (P re-packed from S fragments in registers) ----
#pragma unroll
            for (int kc = 0; kc < 4; kc++) {
                const int j0 = 2 * kc, j1 = 2 * kc + 1;
                uint32_t pah[4], pal[4];
                {
                    __nv_bfloat16 h00 = __float2bfloat16_rn(s[j0][0]);
                    __nv_bfloat16 h01 = __float2bfloat16_rn(s[j0][1]);
                    __nv_bfloat16 h02 = __float2bfloat16_rn(s[j0][2]);
                    __nv_bfloat16 h03 = __float2bfloat16_rn(s[j0][3]);
                    __nv_bfloat16 h10 = __float2bfloat16_rn(s[j1][0]);
                    __nv_bfloat16 h11 = __float2bfloat16_rn(s[j1][1]);
                    __nv_bfloat16 h12 = __float2bfloat16_rn(s[j1][2]);
                    __nv_bfloat16 h13 = __float2bfloat16_rn(s[j1][3]);
                    __nv_bfloat162 t;
                    t = __nv_bfloat162(h00, h01); pah[0] = *(uint32_t*)&t;
                    t = __nv_bfloat162(h02, h03); pah[1] = *(uint32_t*)&t;
                    t = __nv_bfloat162(h10, h11); pah[2] = *(uint32_t*)&t;
                    t = __nv_bfloat162(h12, h13); pah[3] = *(uint32_t*)&t;
                    pal[0] = pack_bf2(s[j0][0] - __bfloat162float(h00),
                                      s[j0][1] - __bfloat162float(h01));
                    pal[1] = pack_bf2(s[j0][2] - __bfloat162float(h02),
                                      s[j0][3] - __bfloat162float(h03));
                    pal[2] = pack_bf2(s[j1][0] - __bfloat162float(h10),
                                      s[j1][1] - __bfloat162float(h11));
                    pal[3] = pack_bf2(s[j1][2] - __bfloat162float(h12),
                                      s[j1][3] - __bfloat162float(h13));
                }
#pragma unroll
                for (int np = 0; np < 4; np++) {
                    uint32_t vbh[4], vbl[4];
                    uint32_t vaddr = (uint32_t)(kc * 16 + vrow) * 144 + np * 32 + vck;
                    ldsm_x4t(vbh, sb + AT_VH(st) + vaddr);
                    ldsm_x4t(vbl, sb + AT_VL(st) + vaddr);
                    mma_bf16(o[np * 2],     pah, &vbh[0]);
                    mma_bf16(o[np * 2],     pah, &vbl[0]);
                    mma_bf16(o[np * 2],     pal, &vbh[0]);
                    mma_bf16(o[np * 2 + 1], pah, &vbh[2]);
                    mma_bf16(o[np * 2 + 1], pah, &vbl[2]);
                    mma_bf16(o[np * 2 + 1], pal, &vbh[2]);
                }
            }
        }
        __syncthreads();
    }

    // ---- epilogue: normalize, split hi/lo, store ----
    const float inv0 = 1.f / l0, inv1 = 1.f / l1;
    const size_t ob = (size_t)(b * T_ + qrow0) * D_ + h * 64;
#pragma unroll
    for (int j = 0; j < 8; j++) {
        int col = j * 8 + 2 * tg;
        float v00 = o[j][0] * inv0, v01 = o[j][1] * inv0;
        float v10 = o[j][2] * inv1, v11 = o[j][3] * inv1;
        __nv_bfloat16 h00 = __float2bfloat16_rn(v00);
        __nv_bfloat16 h01 = __float2bfloat16_rn(v01);
        __nv_bfloat16 h10 = __float2bfloat16_rn(v10);
        __nv_bfloat16 h11 = __float2bfloat16_rn(v11);
        *(__nv_bfloat162*)(Oh + ob + (size_t)g * D_ + col)       = __nv_bfloat162(h00, h01);
        *(__nv_bfloat162*)(Oh + ob + (size_t)(g + 8) * D_ + col) = __nv_bfloat162(h10, h11);
        __nv_bfloat16 l00 = __float2bfloat16_rn(v00 - __bfloat162float(h00));
        __nv_bfloat16 l01 = __float2bfloat16_rn(v01 - __bfloat162float(h01));
        __nv_bfloat16 l10 = __float2bfloat16_rn(v10 - __bfloat162float(h10));
        __nv_bfloat16 l11 = __float2bfloat16_rn(v11 - __bfloat162float(h11));
        *(__nv_bfloat162*)(Ol + ob + (size_t)g * D_ + col)       = __nv_bfloat162(l00, l01);
        *(__nv_bfloat162*)(Ol + ob + (size_t)(g + 8) * D_ + col) = __nv_bfloat162(l10, l11);
    }
}

// ---------------------------------------------------------------------------
// Launch. Inputs: 0:x 1:k_cache 2:v_cache 3:mask 4:Wq 5:bq 6:Wk 7:Wv 8:bv 9:Wo 10:bo
// Output: [out | k_cache | v_cache]
// ---------------------------------------------------------------------------
extern "C" void kernel_launch(void* const* d_in, const int* in_sizes, int n_in,
                              void* d_out, int out_size)
{
    (void)in_sizes; (void)n_in; (void)out_size;
    const float* x   = (const float*)d_in[0];
    const float* Wq  = (const float*)d_in[4];
    const float* bq  = (const float*)d_in[5];
    const float* Wk  = (const float*)d_in[6];
    const float* Wv  = (const float*)d_in[7];
    const float* bvp = (const float*)d_in[8];
    const float* Wo  = (const float*)d_in[9];
    const float* bo  = (const float*)d_in[10];

    float* out = (float*)d_out;
    float* kc  = out + (size_t)MTOT * D_;
    float* vc  = kc  + (size_t)MTOT * D_;

    __nv_bfloat16 *Xh, *Xl, *Qh, *Ql, *Kh, *Kl, *Vh, *Vl, *Ahp, *Alp, *Wth, *Wtl;
    cudaGetSymbolAddress((void**)&Xh,  g_Xh);
    cudaGetSymbolAddress((void**)&Xl,  g_Xl);
    cudaGetSymbolAddress((void**)&Qh,  g_Qh);
    cudaGetSymbolAddress((void**)&Ql,  g_Ql);
    cudaGetSymbolAddress((void**)&Kh,  g_Kh);
    cudaGetSymbolAddress((void**)&Kl,  g_Kl);
    cudaGetSymbolAddress((void**)&Vh,  g_Vh);
    cudaGetSymbolAddress((void**)&Vl,  g_Vl);
    cudaGetSymbolAddress((void**)&Ahp, g_Ah);
    cudaGetSymbolAddress((void**)&Alp, g_Al);
    cudaGetSymbolAddress((void**)&Wth, g_Wth);
    cudaGetSymbolAddress((void**)&Wtl, g_Wtl);

    const size_t WSZ = (size_t)D_ * D_;
    const int NX = MTOT * D_;

    dim3 tg(D_ / 32, D_ / 32), tb(32, 8);
    transpose_split_kernel<<<tg, tb>>>(Wq, Wth + 0 * WSZ, Wtl + 0 * WSZ);
    transpose_split_kernel<<<tg, tb>>>(Wk, Wth + 1 * WSZ, Wtl + 1 * WSZ);
    transpose_split_kernel<<<tg, tb>>>(Wv, Wth + 2 * WSZ, Wtl + 2 * WSZ);
    transpose_split_kernel<<<tg, tb>>>(Wo, Wth + 3 * WSZ, Wtl + 3 * WSZ);
    split_kernel<<<NX / (256 * 4), 256>>>(x, Xh, Xl, NX);

    cudaFuncSetAttribute(gemm_mma_kernel,
                         cudaFuncAttributeMaxDynamicSharedMemorySize, GEMM_SMEM);
    dim3 gg(D_ / 128, MTOT / 128);   // (10, 64)
    // Q: only bf16 split needed
    gemm_mma_kernel<<<gg, 256, GEMM_SMEM>>>(Xh, Xl, Wth + 0 * WSZ, Wtl + 0 * WSZ,
                                            bq, nullptr, Qh, Ql);
    // K: fp32 cache output + bf16 split
    gemm_mma_kernel<<<gg, 256, GEMM_SMEM>>>(Xh, Xl, Wth + 1 * WSZ, Wtl + 1 * WSZ,
                                            nullptr, kc, Kh, Kl);
    // V: fp32 cache output + bf16 split
    gemm_mma_kernel<<<gg, 256, GEMM_SMEM>>>(Xh, Xl, Wth + 2 * WSZ, Wtl + 2 * WSZ,
                                            bvp, vc, Vh, Vl);

    cudaFuncSetAttribute(attn_mma_kernel,
                         cudaFuncAttributeMaxDynamicSharedMemorySize, ATTN_SMEM);
    dim3 ga(B_ * H_, T_ / 128);      // (160, 8)
    attn_mma_kernel<<<ga, 256, ATTN_SMEM>>>(Qh, Ql, Kh, Kl, Vh, Vl, Ahp, Alp);

    // O projection: fp32 final output only
    gemm_mma_kernel<<<gg, 256, GEMM_SMEM>>>(Ahp, Alp, Wth + 3 * WSZ, Wtl + 3 * WSZ,
                                            bo, out, nullptr, nullptr);
}

// round 7
// speedup vs baseline: 3.1528x; 1.4808x over previous
#include <cuda_runtime.h>
#include <cuda_bf16.h>
#include <cuda_fp16.h>
#include <cstdint>

#define B_   8
#define T_   1024
#define D_   1280
#define H_   20
#define MTOT (B_ * T_)   // 8192

// ---------------------------------------------------------------------------
// Scratch (device globals; no allocation allowed)
// ---------------------------------------------------------------------------
__device__ half           g_Xf[(size_t)MTOT * D_];     // x as fp16
__device__ half           g_Wtf[3 * (size_t)D_ * D_];  // Wq/Wk/Wv transposed fp16 [N][K]
__device__ __nv_bfloat16  g_Qh[(size_t)MTOT * D_];
__device__ __nv_bfloat16  g_Ql[(size_t)MTOT * D_];
__device__ __nv_bfloat16  g_Kh[(size_t)MTOT * D_];
__device__ __nv_bfloat16  g_Kl[(size_t)MTOT * D_];
__device__ __nv_bfloat16  g_Vh[(size_t)MTOT * D_];
__device__ __nv_bfloat16  g_Vl[(size_t)MTOT * D_];
__device__ __nv_bfloat16  g_Ah[(size_t)MTOT * D_];     // attention out hi
__device__ __nv_bfloat16  g_Al[(size_t)MTOT * D_];
__device__ __nv_bfloat16  g_Wth[(size_t)D_ * D_];      // Wo transposed, bf16 hi
__device__ __nv_bfloat16  g_Wtl[(size_t)D_ * D_];      // Wo transposed, bf16 lo

// ---------------------------------------------------------------------------
// PTX helpers (plain sm_103 target — NO tcgen05)
// ---------------------------------------------------------------------------
__device__ __forceinline__ uint32_t smem_u32(const void* p) {
    uint32_t a;
    asm("{ .reg .u64 t; cvta.to.shared.u64 t, %1; cvt.u32.u64 %0, t; }"
        : "=r"(a) : "l"(p));
    return a;
}
__device__ __forceinline__ void cpa16(uint32_t dst, const void* src) {
    asm volatile("cp.async.cg.shared.global [%0], [%1], 16;"
                 :: "r"(dst), "l"(src));
}
__device__ __forceinline__ void cpa_commit() {
    asm volatile("cp.async.commit_group;" ::: "memory");
}
__device__ __forceinline__ void cpa_wait0() { asm volatile("cp.async.wait_group 0;" ::: "memory"); }
__device__ __forceinline__ void cpa_wait1() { asm volatile("cp.async.wait_group 1;" ::: "memory"); }
__device__ __forceinline__ void cpa_wait2() { asm volatile("cp.async.wait_group 2;" ::: "memory"); }
__device__ __forceinline__ void ldsm_x4(uint32_t* r, uint32_t addr) {
    asm volatile("ldmatrix.sync.aligned.m8n8.x4.shared.b16 {%0,%1,%2,%3}, [%4];"
                 : "=r"(r[0]), "=r"(r[1]), "=r"(r[2]), "=r"(r[3]) : "r"(addr));
}
__device__ __forceinline__ void ldsm_x4t(uint32_t* r, uint32_t addr) {
    asm volatile("ldmatrix.sync.aligned.m8n8.x4.trans.shared.b16 {%0,%1,%2,%3}, [%4];"
                 : "=r"(r[0]), "=r"(r[1]), "=r"(r[2]), "=r"(r[3]) : "r"(addr));
}
__device__ __forceinline__ void mma_bf16(float* c, const uint32_t* a, const uint32_t* b) {
    asm volatile(
        "mma.sync.aligned.m16n8k16.row.col.f32.bf16.bf16.f32 "
        "{%0,%1,%2,%3}, {%4,%5,%6,%7}, {%8,%9}, {%0,%1,%2,%3};"
        : "+f"(c[0]), "+f"(c[1]), "+f"(c[2]), "+f"(c[3])
        : "r"(a[0]), "r"(a[1]), "r"(a[2]), "r"(a[3]), "r"(b[0]), "r"(b[1]));
}
__device__ __forceinline__ void mma_f16(float* c, const uint32_t* a, const uint32_t* b) {
    asm volatile(
        "mma.sync.aligned.m16n8k16.row.col.f32.f16.f16.f32 "
        "{%0,%1,%2,%3}, {%4,%5,%6,%7}, {%8,%9}, {%0,%1,%2,%3};"
        : "+f"(c[0]), "+f"(c[1]), "+f"(c[2]), "+f"(c[3])
        : "r"(a[0]), "r"(a[1]), "r"(a[2]), "r"(a[3]), "r"(b[0]), "r"(b[1]));
}
__device__ __forceinline__ uint32_t pack_bf2(float x, float y) {
    __nv_bfloat162 t = __floats2bfloat162_rn(x, y);
    return *(uint32_t*)&t;
}

// ---------------------------------------------------------------------------
// Prepass: fp32 -> fp16 (elementwise)
// ---------------------------------------------------------------------------
__global__ __launch_bounds__(256) void tof16_kernel(
    const float* __restrict__ src, half* __restrict__ dst, int n)
{
    int i = (blockIdx.x * 256 + threadIdx.x) * 4;
    if (i >= n) return;
    float4 v = *(const float4*)(src + i);
    half2* dp = (half2*)(dst + i);
    dp[0] = __floats2half2_rn(v.x, v.y);
    dp[1] = __floats2half2_rn(v.z, v.w);
}

// ---------------------------------------------------------------------------
// Prepass: W[k][n] -> Wt[n][k] fp16 (fused transpose + convert)
// ---------------------------------------------------------------------------
__global__ __launch_bounds__(256) void transpose_f16_kernel(
    const float* __restrict__ src, half* __restrict__ dst)
{
    __shared__ float t[32][33];
    int bx = blockIdx.x * 32, by = blockIdx.y * 32;
    int x = bx + threadIdx.x;
    int y = by + threadIdx.y;
#pragma unroll
    for (int i = 0; i < 32; i += 8)
        t[threadIdx.y + i][threadIdx.x] = src[(size_t)(y + i) * D_ + x];
    __syncthreads();
    int x2 = by + threadIdx.x;
    int y2 = bx + threadIdx.y;
#pragma unroll
    for (int i = 0; i < 32; i += 8)
        dst[(size_t)(y2 + i) * D_ + x2] = __float2half_rn(t[threadIdx.x][threadIdx.y + i]);
}

// ---------------------------------------------------------------------------
// Prepass: W[k][n] -> Wt_hi/lo[n][k] bf16 (for Wo, split precision)
// ---------------------------------------------------------------------------
__global__ __launch_bounds__(256) void transpose_split_kernel(
    const float* __restrict__ src,
    __nv_bfloat16* __restrict__ hi, __nv_bfloat16* __restrict__ lo)
{
    __shared__ float t[32][33];
    int bx = blockIdx.x * 32, by = blockIdx.y * 32;
    int x = bx + threadIdx.x;
    int y = by + threadIdx.y;
#pragma unroll
    for (int i = 0; i < 32; i += 8)
        t[threadIdx.y + i][threadIdx.x] = src[(size_t)(y + i) * D_ + x];
    __syncthreads();
    int x2 = by + threadIdx.x;
    int y2 = bx + threadIdx.y;
#pragma unroll
    for (int i = 0; i < 32; i += 8) {
        float v = t[threadIdx.x][threadIdx.y + i];
        __nv_bfloat16 h = __float2bfloat16_rn(v);
        __nv_bfloat16 l = __float2bfloat16_rn(v - __bfloat162float(h));
        hi[(size_t)(y2 + i) * D_ + x2] = h;
        lo[(size_t)(y2 + i) * D_ + x2] = l;
    }
}

// ---------------------------------------------------------------------------
// Shared epilogue: fp32 acc -> optional fp32 C, optional bf16 hi/lo split
// ---------------------------------------------------------------------------
__device__ __forceinline__ void gemm_epilogue(
    float acc[4][4][4], int bm, int bn, int wm, int wn, int lid,
    const float* bias, float* C, __nv_bfloat16* Oh, __nv_bfloat16* Ol)
{
    const int g = lid >> 2, tg = lid & 3;
#pragma unroll
    for (int mt = 0; mt < 4; mt++) {
#pragma unroll
        for (int nt = 0; nt < 4; nt++) {
            int row = bm + wm + mt * 16 + g;
            int col = bn + wn + nt * 8 + tg * 2;
            float b0 = 0.f, b1 = 0.f;
            if (bias) { b0 = bias[col]; b1 = bias[col + 1]; }
            float v00 = acc[mt][nt][0] + b0, v01 = acc[mt][nt][1] + b1;
            float v10 = acc[mt][nt][2] + b0, v11 = acc[mt][nt][3] + b1;
            if (C) {
                *(float2*)(C + (size_t)row * D_ + col)       = make_float2(v00, v01);
                *(float2*)(C + (size_t)(row + 8) * D_ + col) = make_float2(v10, v11);
            }
            if (Oh) {
                __nv_bfloat16 h00 = __float2bfloat16_rn(v00);
                __nv_bfloat16 h01 = __float2bfloat16_rn(v01);
                __nv_bfloat16 h10 = __float2bfloat16_rn(v10);
                __nv_bfloat16 h11 = __float2bfloat16_rn(v11);
                *(__nv_bfloat162*)(Oh + (size_t)row * D_ + col) = __nv_bfloat162(h00, h01);
                *(__nv_bfloat162*)(Oh + (size_t)(row + 8) * D_ + col) = __nv_bfloat162(h10, h11);
                __nv_bfloat16 l00 = __float2bfloat16_rn(v00 - __bfloat162float(h00));
                __nv_bfloat16 l01 = __float2bfloat16_rn(v01 - __bfloat162float(h01));
                __nv_bfloat16 l10 = __float2bfloat16_rn(v10 - __bfloat162float(h10));
                __nv_bfloat16 l11 = __float2bfloat16_rn(v11 - __bfloat162float(h11));
                *(__nv_bfloat162*)(Ol + (size_t)row * D_ + col) = __nv_bfloat162(l00, l01);
                *(__nv_bfloat162*)(Ol + (size_t)(row + 8) * D_ + col) = __nv_bfloat162(l10, l11);
            }
        }
    }
}

// ---------------------------------------------------------------------------
// fp16 single-pass mma.sync GEMM: C = A[M,K] @ Bt[N,K]^T (+bias)
// 128x128 CTA tile, BK=32, 8 warps, cp.async double buffer. 1 mma unit.
// ---------------------------------------------------------------------------
#define SSB  (128 * 40 * 2)           // 10240 B per (array, stage); row = 80 B
#define F16_SMEM (4 * SSB)            // A,B x 2 stages = 40960 B

__global__ __launch_bounds__(256, 2) void gemm_f16_kernel(
    const half* __restrict__ A, const half* __restrict__ Bt,
    const float* __restrict__ bias, float* __restrict__ C,
    __nv_bfloat16* __restrict__ Oh, __nv_bfloat16* __restrict__ Ol)
{
    extern __shared__ char smem[];
    const uint32_t sb = smem_u32(smem);

    const int tid = threadIdx.x;
    const int wid = tid >> 5, lid = tid & 31;
    const int bm = blockIdx.y * 128;
    const int bn = blockIdx.x * 128;
    const int wm = (wid >> 2) * 64;
    const int wn = (wid & 3) * 32;

    const int lrow  = tid >> 1;
    const int lseg  = (tid & 1) * 16;

    const int arow = lid & 15;
    const int ak   = (lid >> 4) * 16;
    const int bgrp = lid >> 3;
    const int brow = (lid & 7) + ((bgrp >> 1) << 3);
    const int bk   = (bgrp & 1) * 16;

    float acc[4][4][4];
#pragma unroll
    for (int i = 0; i < 4; i++)
#pragma unroll
        for (int j = 0; j < 4; j++)
#pragma unroll
            for (int k = 0; k < 4; k++) acc[i][j][k] = 0.f;

#define FST_(arr, stage) (sb + ((arr) * 2 + (stage)) * SSB)

#define FLOADSTAGE(kb, stage)                                                  \
    {                                                                          \
        size_t ga = (size_t)(bm + lrow) * D_ + (kb) * 32 + lseg / 2;           \
        size_t gb = (size_t)(bn + lrow) * D_ + (kb) * 32 + lseg / 2;           \
        uint32_t so = (uint32_t)(lrow * 80 + lseg);                            \
        cpa16(FST_(0, stage) + so,      A  + ga);                              \
        cpa16(FST_(0, stage) + so + 32, A  + ga + 16);                         \
        cpa16(FST_(1, stage) + so,      Bt + gb);                              \
        cpa16(FST_(1, stage) + so + 32, Bt + gb + 16);                         \
        cpa_commit();                                                          \
    }

    FLOADSTAGE(0, 0);

    for (int kb = 0; kb < 40; kb++) {
        const int st = kb & 1;
        if (kb < 39) { FLOADSTAGE(kb + 1, st ^ 1); cpa_wait1(); }
        else         { cpa_wait0(); }
        __syncthreads();

        const uint32_t aB = FST_(0, st), bB = FST_(1, st);
#pragma unroll
        for (int kk = 0; kk < 2; kk++) {
            const uint32_t ko = kk * 32;
            uint32_t bh[8];
            ldsm_x4(&bh[0], bB + (uint32_t)(wn + brow)      * 80 + bk + ko);
            ldsm_x4(&bh[4], bB + (uint32_t)(wn + 16 + brow) * 80 + bk + ko);
#pragma unroll
            for (int mt = 0; mt < 4; mt++) {
                uint32_t ah[4];
                ldsm_x4(ah, aB + (uint32_t)(wm + mt * 16 + arow) * 80 + ak + ko);
#pragma unroll
                for (int nt = 0; nt < 4; nt++)
                    mma_f16(acc[mt][nt], ah, &bh[nt * 2]);
            }
        }
        __syncthreads();
    }

    gemm_epilogue(acc, bm, bn, wm, wn, lid, bias, C, Oh, Ol);
}

// ---------------------------------------------------------------------------
// bf16x3 mma.sync GEMM (split precision) — used for O projection only.
// ---------------------------------------------------------------------------
#define GEMM_SMEM (8 * SSB)           // 4 arrays x 2 stages = 81920 B

__global__ __launch_bounds__(256, 2) void gemm_mma_kernel(
    const __nv_bfloat16* __restrict__ Ah, const __nv_bfloat16* __restrict__ Al,
    const __nv_bfloat16* __restrict__ Bh, const __nv_bfloat16* __restrict__ Bl,
    const float* __restrict__ bias, float* __restrict__ C,
    __nv_bfloat16* __restrict__ Oh, __nv_bfloat16* __restrict__ Ol)
{
    extern __shared__ char smem[];
    const uint32_t sb = smem_u32(smem);

    const int tid = threadIdx.x;
    const int wid = tid >> 5, lid = tid & 31;
    const int bm = blockIdx.y * 128;
    const int bn = blockIdx.x * 128;
    const int wm = (wid >> 2) * 64;
    const int wn = (wid & 3) * 32;

    const int lrow  = tid >> 1;
    const int lseg  = (tid & 1) * 16;

    const int arow = lid & 15;
    const int ak   = (lid >> 4) * 16;
    const int bgrp = lid >> 3;
    const int brow = (lid & 7) + ((bgrp >> 1) << 3);
    const int bk   = (bgrp & 1) * 16;

    float acc[4][4][4];
#pragma unroll
    for (int i = 0; i < 4; i++)
#pragma unroll
        for (int j = 0; j < 4; j++)
#pragma unroll
            for (int k = 0; k < 4; k++) acc[i][j][k] = 0.f;

#define STG_(arr, stage) (sb + ((arr) * 2 + (stage)) * SSB)

#define LOADSTAGE(kb, stage)                                                   \
    {                                                                          \
        size_t ga = (size_t)(bm + lrow) * D_ + (kb) * 32 + lseg / 2;           \
        size_t gb = (size_t)(bn + lrow) * D_ + (kb) * 32 + lseg / 2;           \
        uint32_t so = (uint32_t)(lrow * 80 + lseg);                            \
        cpa16(STG_(0, stage) + so,      Ah + ga);                              \
        cpa16(STG_(0, stage) + so + 32, Ah + ga + 16);                         \
        cpa16(STG_(1, stage) + so,      Al + ga);                              \
        cpa16(STG_(1, stage) + so + 32, Al + ga + 16);                         \
        cpa16(STG_(2, stage) + so,      Bh + gb);                              \
        cpa16(STG_(2, stage) + so + 32, Bh + gb + 16);                         \
        cpa16(STG_(3, stage) + so,      Bl + gb);                              \
        cpa16(STG_(3, stage) + so + 32, Bl + gb + 16);                         \
        cpa_commit();                                                          \
    }

    LOADSTAGE(0, 0);

    for (int kb = 0; kb < 40; kb++) {
        const int st = kb & 1;
        if (kb < 39) { LOADSTAGE(kb + 1, st ^ 1); cpa_wait1(); }
        else         { cpa_wait0(); }
        __syncthreads();

        const uint32_t aB  = STG_(0, st), alB = STG_(1, st);
        const uint32_t bB  = STG_(2, st), blB = STG_(3, st);
#pragma unroll
        for (int kk = 0; kk < 2; kk++) {
            const uint32_t ko = kk * 32;
            uint32_t bh[8], bl[8];
            ldsm_x4(&bh[0], bB  + (uint32_t)(wn + brow)      * 80 + bk + ko);
            ldsm_x4(&bh[4], bB  + (uint32_t)(wn + 16 + brow) * 80 + bk + ko);
            ldsm_x4(&bl[0], blB + (uint32_t)(wn + brow)      * 80 + bk + ko);
            ldsm_x4(&bl[4], blB + (uint32_t)(wn + 16 + brow) * 80 + bk + ko);
#pragma unroll
            for (int mt = 0; mt < 4; mt++) {
                uint32_t ah[4], alr[4];
                ldsm_x4(ah,  aB  + (uint32_t)(wm + mt * 16 + arow) * 80 + ak + ko);
                ldsm_x4(alr, alB + (uint32_t)(wm + mt * 16 + arow) * 80 + ak + ko);
#pragma unroll
                for (int nt = 0; nt < 4; nt++) {
                    mma_bf16(acc[mt][nt], ah,  &bh[nt * 2]);
                    mma_bf16(acc[mt][nt], ah,  &bl[nt * 2]);
                    mma_bf16(acc[mt][nt], alr, &bh[nt * 2]);
                }
            }
        }
        __syncthreads();
    }

    gemm_epilogue(acc, bm, bn, wm, wn, lid, bias, C, Oh, Ol);
}

// ---------------------------------------------------------------------------
// Causal flash attention via mma.sync (bf16 split precision). Unchanged R6.
// ---------------------------------------------------------------------------
#define AT_QH 0
#define AT_QL 18432
#define AT_KH(st) (36864  + (st) * 9216)
#define AT_KL(st) (64512  + (st) * 9216)
#define AT_VH(st) (92160  + (st) * 9216)
#define AT_VL(st) (119808 + (st) * 9216)
#define ATTN_SMEM 147456

__global__ __launch_bounds__(256, 1) void attn_mma_kernel(
    const __nv_bfloat16* __restrict__ Qh, const __nv_bfloat16* __restrict__ Ql,
    const __nv_bfloat16* __restrict__ Kh, const __nv_bfloat16* __restrict__ Kl,
    const __nv_bfloat16* __restrict__ Vh, const __nv_bfloat16* __restrict__ Vl,
    __nv_bfloat16* __restrict__ Oh, __nv_bfloat16* __restrict__ Ol)
{
    extern __shared__ char smem[];
    const uint32_t sb = smem_u32(smem);

    const int tid = threadIdx.x;
    const int wid = tid >> 5, lid = tid & 31;
    const int bh = blockIdx.x;
    const int b  = bh / H_;
    const int h  = bh % H_;
    const int qb = blockIdx.y;
    const int nkt = 2 * qb + 2;

    const int g  = lid >> 2, tg = lid & 3;
    const int wr = wid * 16;
    const int qrow0 = qb * 128 + wr;

    const int arow = lid & 15;
    const int ak   = (lid >> 4) * 16;
    const int bgrp = lid >> 3;
    const int brow = (lid & 7) + ((bgrp >> 1) << 3);
    const int bk   = (bgrp & 1) * 16;
    const int vrow = (lid & 7) + ((bgrp & 1) << 3);
    const int vck  = (lid >> 4) * 16;

    {
        const size_t qgbase = (size_t)(b * T_ + qb * 128) * D_ + h * 64;
#pragma unroll
        for (int i = 0; i < 4; i++) {
            int id = tid + i * 256;
            int r = id >> 3, e = (id & 7) * 8;
            uint32_t so = (uint32_t)(r * 144 + e * 2);
            cpa16(sb + AT_QH + so, Qh + qgbase + (size_t)r * D_ + e);
            cpa16(sb + AT_QL + so, Ql + qgbase + (size_t)r * D_ + e);
        }
    }
#define LOADKV(kt, st)                                                         \
    {                                                                          \
        const size_t kvb = (size_t)(b * T_ + (kt) * 64) * D_ + h * 64;         \
        _Pragma("unroll")                                                      \
        for (int i = 0; i < 2; i++) {                                          \
            int id = tid + i * 256;                                            \
            int r = id >> 3, e = (id & 7) * 8;                                 \
            uint32_t so = (uint32_t)(r * 144 + e * 2);                         \
            size_t go = kvb + (size_t)r * D_ + e;                              \
            cpa16(sb + AT_KH(st) + so, Kh + go);                               \
            cpa16(sb + AT_KL(st) + so, Kl + go);                               \
            cpa16(sb + AT_VH(st) + so, Vh + go);                               \
            cpa16(sb + AT_VL(st) + so, Vl + go);                               \
        }                                                                      \
        cpa_commit();                                                          \
    }
    LOADKV(0, 0);
    if (nkt > 1) LOADKV(1, 1);

    float m0 = -1e30f, m1 = -1e30f, l0 = 0.f, l1 = 0.f;
    float o[8][4];
#pragma unroll
    for (int j = 0; j < 8; j++)
#pragma unroll
        for (int e = 0; e < 4; e++) o[j][e] = 0.f;

    for (int kt = 0; kt < nkt; kt++) {
        const int st = kt % 3;
        if (kt + 2 < nkt) { LOADKV(kt + 2, (kt + 2) % 3); cpa_wait2(); }
        else if (kt + 1 < nkt) cpa_wait1();
        else cpa_wait0();
        __syncthreads();

        if (kt * 64 <= qrow0 + 15) {
            float s[8][4];
#pragma unroll
            for (int j = 0; j < 8; j++)
#pragma unroll
                for (int e = 0; e < 4; e++) s[j][e] = 0.f;

#pragma unroll
            for (int kc = 0; kc < 4; kc++) {
                uint32_t ah[4], al[4];
                ldsm_x4(ah, sb + AT_QH + (uint32_t)(wr + arow) * 144 + kc * 32 + ak);
                ldsm_x4(al, sb + AT_QL + (uint32_t)(wr + arow) * 144 + kc * 32 + ak);
#pragma unroll
                for (int np = 0; np < 4; np++) {
                    uint32_t kbh[4], kbl[4];
                    ldsm_x4(kbh, sb + AT_KH(st) + (uint32_t)(np * 16 + brow) * 144 + kc * 32 + bk);
                    ldsm_x4(kbl, sb + AT_KL(st) + (uint32_t)(np * 16 + brow) * 144 + kc * 32 + bk);
                    mma_bf16(s[np * 2],     ah, &kbh[0]);
                    mma_bf16(s[np * 2],     ah, &kbl[0]);
                    mma_bf16(s[np * 2],     al, &kbh[0]);
                    mma_bf16(s[np * 2 + 1], ah, &kbh[2]);
                    mma_bf16(s[np * 2 + 1], ah, &kbl[2]);
                    mma_bf16(s[np * 2 + 1], al, &kbh[2]);
                }
            }

            const int r0 = qrow0 + g, r1 = r0 + 8;
#pragma unroll
            for (int j = 0; j < 8; j++) {
                int c0 = kt * 64 + j * 8 + 2 * tg;
                s[j][0] = (c0     <= r0) ? s[j][0] * 0.125f : -1e30f;
                s[j][1] = (c0 + 1 <= r0) ? s[j][1] * 0.125f : -1e30f;
                s[j][2] = (c0     <= r1) ? s[j][2] * 0.125f : -1e30f;
                s[j][3] = (c0 + 1 <= r1) ? s[j][3] * 0.125f : -1e30f;
            }

            float mx0 = -1e30f, mx1 = -1e30f;
#pragma unroll
            for (int j = 0; j < 8; j++) {
                mx0 = fmaxf(mx0, fmaxf(s[j][0], s[j][1]));
                mx1 = fmaxf(mx1, fmaxf(s[j][2], s[j][3]));
            }
            mx0 = fmaxf(mx0, __shfl_xor_sync(0xffffffffu, mx0, 1));
            mx0 = fmaxf(mx0, __shfl_xor_sync(0xffffffffu, mx0, 2));
            mx1 = fmaxf(mx1, __shfl_xor_sync(0xffffffffu, mx1, 1));
            mx1 = fmaxf(mx1, __shfl_xor_sync(0xffffffffu, mx1, 2));
            float mn0 = fmaxf(m0, mx0), mn1 = fmaxf(m1, mx1);
            float f0 = __expf(m0 - mn0), f1 = __expf(m1 - mn1);
            m0 = mn0; m1 = mn1;
            float rs0 = 0.f, rs1 = 0.f;
#pragma unroll
            for (int j = 0; j < 8; j++) {
                s[j][0] = __expf(s[j][0] - mn0);
                s[j][1] = __expf(s[j][1] - mn0);
                s[j][2] = __expf(s[j][2] - mn1);
                s[j][3] = __expf(s[j][3] - mn1);
                rs0 += s[j][0] + s[j][1];
                rs1 += s[j][2] + s[j][3];
            }
            rs0 += __shfl_xor_sync(0xffffffffu, rs0, 1);
            rs0 += __shfl_xor_sync(0xffffffffu, rs0, 2);
            rs1 += __shfl_xor_sync(0xffffffffu, rs1, 1);
            rs1 += __shfl_xor_sync(0xffffffffu, rs1, 2);
            l0 = l0 * f0 + rs0;
            l1 = l1 * f1 + rs1;
#pragma unroll
            for (int j = 0; j < 8; j++) {
                o[j][0] *= f0; o[j][1] *= f0;
                o[j][2] *= f1; o[j][3] *= f1;
            }

#pragma unroll
            for (int kc = 0; kc < 4; kc++) {
                const int j0 = 2 * kc, j1 = 2 * kc + 1;
                uint32_t pah[4], pal[4];
                {
                    __nv_bfloat16 h00 = __float2bfloat16_rn(s[j0][0]);
                    __nv_bfloat16 h01 = __float2bfloat16_rn(s[j0][1]);
                    __nv_bfloat16 h02 = __float2bfloat16_rn(s[j0][2]);
                    __nv_bfloat16 h03 = __float2bfloat16_rn(s[j0][3]);
                    __nv_bfloat16 h10 = __float2bfloat16_rn(s[j1][0]);
                    __nv_bfloat16 h11 = __float2bfloat16_rn(s[j1][1]);
                    __nv_bfloat16 h12 = __float2bfloat16_rn(s[j1][2]);
                    __nv_bfloat16 h13 = __float2bfloat16_rn(s[j1][3]);
                    __nv_bfloat162 t;
                    t = __nv_bfloat162(h00, h01); pah[0] = *(uint32_t*)&t;
                    t = __nv_bfloat162(h02, h03); pah[1] = *(uint32_t*)&t;
                    t = __nv_bfloat162(h10, h11); pah[2] = *(uint32_t*)&t;
                    t = __nv_bfloat162(h12, h13); pah[3] = *(uint32_t*)&t;
                    pal[0] = pack_bf2(s[j0][0] - __bfloat162float(h00),
                                      s[j0][1] - __bfloat162float(h01));
                    pal[1] = pack_bf2(s[j0][2] - __bfloat162float(h02),
                                      s[j0][3] - __bfloat162float(h03));
                    pal[2] = pack_bf2(s[j1][0] - __bfloat162float(h10),
                                      s[j1][1] - __bfloat162float(h11));
                    pal[3] = pack_bf2(s[j1][2] - __bfloat162float(h12),
                                      s[j1][3] - __bfloat162float(h13));
                }
#pragma unroll
                for (int np = 0; np < 4; np++) {
                    uint32_t vbh[4], vbl[4];
                    uint32_t vaddr = (uint32_t)(kc * 16 + vrow) * 144 + np * 32 + vck;
                    ldsm_x4t(vbh, sb + AT_VH(st) + vaddr);
                    ldsm_x4t(vbl, sb + AT_VL(st) + vaddr);
                    mma_bf16(o[np * 2],     pah, &vbh[0]);
                    mma_bf16(o[np * 2],     pah, &vbl[0]);
                    mma_bf16(o[np * 2],     pal, &vbh[0]);
                    mma_bf16(o[np * 2 + 1], pah, &vbh[2]);
                    mma_bf16(o[np * 2 + 1], pah, &vbl[2]);
                    mma_bf16(o[np * 2 + 1], pal, &vbh[2]);
                }
            }
        }
        __syncthreads();
    }

    const float inv0 = 1.f / l0, inv1 = 1.f / l1;
    const size_t ob = (size_t)(b * T_ + qrow0) * D_ + h * 64;
#pragma unroll
    for (int j = 0; j < 8; j++) {
        int col = j * 8 + 2 * tg;
        float v00 = o[j][0] * inv0, v01 = o[j][1] * inv0;
        float v10 = o[j][2] * inv1, v11 = o[j][3] * inv1;
        __nv_bfloat16 h00 = __float2bfloat16_rn(v00);
        __nv_bfloat16 h01 = __float2bfloat16_rn(v01);
        __nv_bfloat16 h10 = __float2bfloat16_rn(v10);
        __nv_bfloat16 h11 = __float2bfloat16_rn(v11);
        *(__nv_bfloat162*)(Oh + ob + (size_t)g * D_ + col)       = __nv_bfloat162(h00, h01);
        *(__nv_bfloat162*)(Oh + ob + (size_t)(g + 8) * D_ + col) = __nv_bfloat162(h10, h11);
        __nv_bfloat16 l00 = __float2bfloat16_rn(v00 - __bfloat162float(h00));
        __nv_bfloat16 l01 = __float2bfloat16_rn(v01 - __bfloat162float(h01));
        __nv_bfloat16 l10 = __float2bfloat16_rn(v10 - __bfloat162float(h10));
        __nv_bfloat16 l11 = __float2bfloat16_rn(v11 - __bfloat162float(h11));
        *(__nv_bfloat162*)(Ol + ob + (size_t)g * D_ + col)       = __nv_bfloat162(l00, l01);
        *(__nv_bfloat162*)(Ol + ob + (size_t)(g + 8) * D_ + col) = __nv_bfloat162(l10, l11);
    }
}

// ---------------------------------------------------------------------------
// Launch. Inputs: 0:x 1:k_cache 2:v_cache 3:mask 4:Wq 5:bq 6:Wk 7:Wv 8:bv 9:Wo 10:bo
// Output: [out | k_cache | v_cache]
// ---------------------------------------------------------------------------
extern "C" void kernel_launch(void* const* d_in, const int* in_sizes, int n_in,
                              void* d_out, int out_size)
{
    (void)in_sizes; (void)n_in; (void)out_size;
    const float* x   = (const float*)d_in[0];
    const float* Wq  = (const float*)d_in[4];
    const float* bq  = (const float*)d_in[5];
    const float* Wk  = (const float*)d_in[6];
    const float* Wv  = (const float*)d_in[7];
    const float* bvp = (const float*)d_in[8];
    const float* Wo  = (const float*)d_in[9];
    const float* bo  = (const float*)d_in[10];

    float* out = (float*)d_out;
    float* kc  = out + (size_t)MTOT * D_;
    float* vc  = kc  + (size_t)MTOT * D_;

    half *Xf, *Wtf;
    __nv_bfloat16 *Qh, *Ql, *Kh, *Kl, *Vh, *Vl, *Ahp, *Alp, *Wth, *Wtl;
    cudaGetSymbolAddress((void**)&Xf,  g_Xf);
    cudaGetSymbolAddress((void**)&Wtf, g_Wtf);
    cudaGetSymbolAddress((void**)&Qh,  g_Qh);
    cudaGetSymbolAddress((void**)&Ql,  g_Ql);
    cudaGetSymbolAddress((void**)&Kh,  g_Kh);
    cudaGetSymbolAddress((void**)&Kl,  g_Kl);
    cudaGetSymbolAddress((void**)&Vh,  g_Vh);
    cudaGetSymbolAddress((void**)&Vl,  g_Vl);
    cudaGetSymbolAddress((void**)&Ahp, g_Ah);
    cudaGetSymbolAddress((void**)&Alp, g_Al);
    cudaGetSymbolAddress((void**)&Wth, g_Wth);
    cudaGetSymbolAddress((void**)&Wtl, g_Wtl);

    const size_t WSZ = (size_t)D_ * D_;
    const int NX = MTOT * D_;

    dim3 tg(D_ / 32, D_ / 32), tb(32, 8);
    transpose_f16_kernel<<<tg, tb>>>(Wq, Wtf + 0 * WSZ);
    transpose_f16_kernel<<<tg, tb>>>(Wk, Wtf + 1 * WSZ);
    transpose_f16_kernel<<<tg, tb>>>(Wv, Wtf + 2 * WSZ);
    transpose_split_kernel<<<tg, tb>>>(Wo, Wth, Wtl);
    tof16_kernel<<<NX / (256 * 4), 256>>>(x, Xf, NX);

    cudaFuncSetAttribute(gemm_f16_kernel,
                         cudaFuncAttributeMaxDynamicSharedMemorySize, F16_SMEM);
    cudaFuncSetAttribute(gemm_mma_kernel,
                         cudaFuncAttributeMaxDynamicSharedMemorySize, GEMM_SMEM);
    dim3 gg(D_ / 128, MTOT / 128);   // (10, 64)

    // Q/K/V projections: single-pass fp16 tensor-core GEMMs
    gemm_f16_kernel<<<gg, 256, F16_SMEM>>>(Xf, Wtf + 0 * WSZ, bq,      nullptr, Qh, Ql);
    gemm_f16_kernel<<<gg, 256, F16_SMEM>>>(Xf, Wtf + 1 * WSZ, nullptr, kc,      Kh, Kl);
    gemm_f16_kernel<<<gg, 256, F16_SMEM>>>(Xf, Wtf + 2 * WSZ, bvp,     vc,      Vh, Vl);

    cudaFuncSetAttribute(attn_mma_kernel,
                         cudaFuncAttributeMaxDynamicSharedMemorySize, ATTN_SMEM);
    dim3 ga(B_ * H_, T_ / 128);      // (160, 8)
    attn_mma_kernel<<<ga, 256, ATTN_SMEM>>>(Qh, Ql, Kh, Kl, Vh, Vl, Ahp, Alp);

    // O projection: bf16x3 split precision (error-critical path)
    gemm_mma_kernel<<<gg, 256, GEMM_SMEM>>>(Ahp, Alp, Wth, Wtl, bo, out,
                                            nullptr, nullptr);
}

// round 8
// speedup vs baseline: 4.5349x; 1.4384x over previous
#include <cuda_runtime.h>
#include <cuda_fp16.h>
#include <cstdint>

#define B_   8
#define T_   1024
#define D_   1280
#define H_   20
#define MTOT (B_ * T_)   // 8192

// ---------------------------------------------------------------------------
// Scratch (device globals; no allocation allowed)
// ---------------------------------------------------------------------------
__device__ half g_Xf[(size_t)MTOT * D_];      // x as fp16
__device__ half g_Wtf[4 * (size_t)D_ * D_];   // Wq/Wk/Wv/Wo transposed fp16 [N][K]
__device__ half g_Qf[(size_t)MTOT * D_];
__device__ half g_Kf[(size_t)MTOT * D_];
__device__ half g_Vf[(size_t)MTOT * D_];
__device__ half g_Af[(size_t)MTOT * D_];      // attention out fp16

// ---------------------------------------------------------------------------
// PTX helpers (plain sm_103 target — NO tcgen05)
// ---------------------------------------------------------------------------
__device__ __forceinline__ uint32_t smem_u32(const void* p) {
    uint32_t a;
    asm("{ .reg .u64 t; cvta.to.shared.u64 t, %1; cvt.u32.u64 %0, t; }"
        : "=r"(a) : "l"(p));
    return a;
}
__device__ __forceinline__ void cpa16(uint32_t dst, const void* src) {
    asm volatile("cp.async.cg.shared.global [%0], [%1], 16;"
                 :: "r"(dst), "l"(src));
}
__device__ __forceinline__ void cpa_commit() {
    asm volatile("cp.async.commit_group;" ::: "memory");
}
__device__ __forceinline__ void cpa_wait0() { asm volatile("cp.async.wait_group 0;" ::: "memory"); }
__device__ __forceinline__ void cpa_wait1() { asm volatile("cp.async.wait_group 1;" ::: "memory"); }
__device__ __forceinline__ void cpa_wait2() { asm volatile("cp.async.wait_group 2;" ::: "memory"); }
__device__ __forceinline__ void ldsm_x4(uint32_t* r, uint32_t addr) {
    asm volatile("ldmatrix.sync.aligned.m8n8.x4.shared.b16 {%0,%1,%2,%3}, [%4];"
                 : "=r"(r[0]), "=r"(r[1]), "=r"(r[2]), "=r"(r[3]) : "r"(addr));
}
__device__ __forceinline__ void ldsm_x4t(uint32_t* r, uint32_t addr) {
    asm volatile("ldmatrix.sync.aligned.m8n8.x4.trans.shared.b16 {%0,%1,%2,%3}, [%4];"
                 : "=r"(r[0]), "=r"(r[1]), "=r"(r[2]), "=r"(r[3]) : "r"(addr));
}
__device__ __forceinline__ void mma_f16(float* c, const uint32_t* a, const uint32_t* b) {
    asm volatile(
        "mma.sync.aligned.m16n8k16.row.col.f32.f16.f16.f32 "
        "{%0,%1,%2,%3}, {%4,%5,%6,%7}, {%8,%9}, {%0,%1,%2,%3};"
        : "+f"(c[0]), "+f"(c[1]), "+f"(c[2]), "+f"(c[3])
        : "r"(a[0]), "r"(a[1]), "r"(a[2]), "r"(a[3]), "r"(b[0]), "r"(b[1]));
}
__device__ __forceinline__ uint32_t pack_h2(float x, float y) {
    half2 t = __floats2half2_rn(x, y);
    return *(uint32_t*)&t;
}

// ---------------------------------------------------------------------------
// Prepass: fp32 -> fp16 (elementwise)
// ---------------------------------------------------------------------------
__global__ __launch_bounds__(256) void tof16_kernel(
    const float* __restrict__ src, half* __restrict__ dst, int n)
{
    int i = (blockIdx.x * 256 + threadIdx.x) * 4;
    if (i >= n) return;
    float4 v = *(const float4*)(src + i);
    half2* dp = (half2*)(dst + i);
    dp[0] = __floats2half2_rn(v.x, v.y);
    dp[1] = __floats2half2_rn(v.z, v.w);
}

// ---------------------------------------------------------------------------
// Prepass: W[k][n] -> Wt[n][k] fp16 (fused transpose + convert)
// ---------------------------------------------------------------------------
__global__ __launch_bounds__(256) void transpose_f16_kernel(
    const float* __restrict__ src, half* __restrict__ dst)
{
    __shared__ float t[32][33];
    int bx = blockIdx.x * 32, by = blockIdx.y * 32;
    int x = bx + threadIdx.x;
    int y = by + threadIdx.y;
#pragma unroll
    for (int i = 0; i < 32; i += 8)
        t[threadIdx.y + i][threadIdx.x] = src[(size_t)(y + i) * D_ + x];
    __syncthreads();
    int x2 = by + threadIdx.x;
    int y2 = bx + threadIdx.y;
#pragma unroll
    for (int i = 0; i < 32; i += 8)
        dst[(size_t)(y2 + i) * D_ + x2] = __float2half_rn(t[threadIdx.x][threadIdx.y + i]);
}

// ---------------------------------------------------------------------------
// fp16 single-pass mma.sync GEMM: C = A[M,K] @ Bt[N,K]^T (+bias)
// 128x128 CTA tile, BK=32, 8 warps, cp.async double buffer.
// Outputs: optional fp32 C, optional fp16 Of.
// ---------------------------------------------------------------------------
#define SSB  (128 * 40 * 2)           // 10240 B per (array, stage); row = 80 B
#define F16_SMEM (4 * SSB)            // A,B x 2 stages = 40960 B

__global__ __launch_bounds__(256, 2) void gemm_f16_kernel(
    const half* __restrict__ A, const half* __restrict__ Bt,
    const float* __restrict__ bias, float* __restrict__ C,
    half* __restrict__ Of)
{
    extern __shared__ char smem[];
    const uint32_t sb = smem_u32(smem);

    const int tid = threadIdx.x;
    const int wid = tid >> 5, lid = tid & 31;
    const int bm = blockIdx.y * 128;
    const int bn = blockIdx.x * 128;
    const int wm = (wid >> 2) * 64;
    const int wn = (wid & 3) * 32;

    const int lrow  = tid >> 1;
    const int lseg  = (tid & 1) * 16;

    const int arow = lid & 15;
    const int ak   = (lid >> 4) * 16;
    const int bgrp = lid >> 3;
    const int brow = (lid & 7) + ((bgrp >> 1) << 3);
    const int bk   = (bgrp & 1) * 16;

    float acc[4][4][4];
#pragma unroll
    for (int i = 0; i < 4; i++)
#pragma unroll
        for (int j = 0; j < 4; j++)
#pragma unroll
            for (int k = 0; k < 4; k++) acc[i][j][k] = 0.f;

#define FST_(arr, stage) (sb + ((arr) * 2 + (stage)) * SSB)

#define FLOADSTAGE(kb, stage)                                                  \
    {                                                                          \
        size_t ga = (size_t)(bm + lrow) * D_ + (kb) * 32 + lseg / 2;           \
        size_t gb = (size_t)(bn + lrow) * D_ + (kb) * 32 + lseg / 2;           \
        uint32_t so = (uint32_t)(lrow * 80 + lseg);                            \
        cpa16(FST_(0, stage) + so,      A  + ga);                              \
        cpa16(FST_(0, stage) + so + 32, A  + ga + 16);                         \
        cpa16(FST_(1, stage) + so,      Bt + gb);                              \
        cpa16(FST_(1, stage) + so + 32, Bt + gb + 16);                         \
        cpa_commit();                                                          \
    }

    FLOADSTAGE(0, 0);

    for (int kb = 0; kb < 40; kb++) {
        const int st = kb & 1;
        if (kb < 39) { FLOADSTAGE(kb + 1, st ^ 1); cpa_wait1(); }
        else         { cpa_wait0(); }
        __syncthreads();

        const uint32_t aB = FST_(0, st), bB = FST_(1, st);
#pragma unroll
        for (int kk = 0; kk < 2; kk++) {
            const uint32_t ko = kk * 32;
            uint32_t bh[8];
            ldsm_x4(&bh[0], bB + (uint32_t)(wn + brow)      * 80 + bk + ko);
            ldsm_x4(&bh[4], bB + (uint32_t)(wn + 16 + brow) * 80 + bk + ko);
#pragma unroll
            for (int mt = 0; mt < 4; mt++) {
                uint32_t ah[4];
                ldsm_x4(ah, aB + (uint32_t)(wm + mt * 16 + arow) * 80 + ak + ko);
#pragma unroll
                for (int nt = 0; nt < 4; nt++)
                    mma_f16(acc[mt][nt], ah, &bh[nt * 2]);
            }
        }
        __syncthreads();
    }

    // Epilogue
    const int g = lid >> 2, tg = lid & 3;
#pragma unroll
    for (int mt = 0; mt < 4; mt++) {
#pragma unroll
        for (int nt = 0; nt < 4; nt++) {
            int row = bm + wm + mt * 16 + g;
            int col = bn + wn + nt * 8 + tg * 2;
            float b0 = 0.f, b1 = 0.f;
            if (bias) { b0 = bias[col]; b1 = bias[col + 1]; }
            float v00 = acc[mt][nt][0] + b0, v01 = acc[mt][nt][1] + b1;
            float v10 = acc[mt][nt][2] + b0, v11 = acc[mt][nt][3] + b1;
            if (C) {
                *(float2*)(C + (size_t)row * D_ + col)       = make_float2(v00, v01);
                *(float2*)(C + (size_t)(row + 8) * D_ + col) = make_float2(v10, v11);
            }
            if (Of) {
                *(half2*)(Of + (size_t)row * D_ + col)       = __floats2half2_rn(v00, v01);
                *(half2*)(Of + (size_t)(row + 8) * D_ + col) = __floats2half2_rn(v10, v11);
            }
        }
    }
}

// ---------------------------------------------------------------------------
// Causal flash attention via mma.sync, fp16 operands, fp32 accum/softmax.
// CTA: 128 q-rows of one (b,h); 8 warps x 16 rows. kv tiles of 64 rows.
// 3-stage cp.async pipeline. smem row stride = 72 fp16 (144 B).
// ---------------------------------------------------------------------------
#define AF_Q 0
#define AF_K(st) (18432 + (st) * 9216)
#define AF_V(st) (46080 + (st) * 9216)
#define ATTN_SMEM 73728

__global__ __launch_bounds__(256, 1) void attn_f16_kernel(
    const half* __restrict__ Qf, const half* __restrict__ Kf,
    const half* __restrict__ Vf, half* __restrict__ Af)
{
    extern __shared__ char smem[];
    const uint32_t sb = smem_u32(smem);

    const int tid = threadIdx.x;
    const int wid = tid >> 5, lid = tid & 31;
    const int bh = blockIdx.x;
    const int b  = bh / H_;
    const int h  = bh % H_;
    const int qb = (gridDim.y - 1) - blockIdx.y;   // heavy blocks first
    const int nkt = 2 * qb + 2;

    const int g  = lid >> 2, tg = lid & 3;
    const int wr = wid * 16;
    const int qrow0 = qb * 128 + wr;

    const int arow = lid & 15;
    const int ak   = (lid >> 4) * 16;
    const int bgrp = lid >> 3;
    const int brow = (lid & 7) + ((bgrp >> 1) << 3);
    const int bk   = (bgrp & 1) * 16;
    const int vrow = (lid & 7) + ((bgrp & 1) << 3);
    const int vck  = (lid >> 4) * 16;

    // ---- prologue: Q + kv stage 0 (group 0), kv stage 1 (group 1) ----
    {
        const size_t qgbase = (size_t)(b * T_ + qb * 128) * D_ + h * 64;
#pragma unroll
        for (int i = 0; i < 4; i++) {
            int id = tid + i * 256;            // 0..1023
            int r = id >> 3, e = (id & 7) * 8;
            cpa16(sb + AF_Q + (uint32_t)(r * 144 + e * 2), Qf + qgbase + (size_t)r * D_ + e);
        }
    }
#define LOADKV(kt, st)                                                         \
    {                                                                          \
        const size_t kvb = (size_t)(b * T_ + (kt) * 64) * D_ + h * 64;         \
        _Pragma("unroll")                                                      \
        for (int i = 0; i < 2; i++) {                                          \
            int id = tid + i * 256;                                            \
            int r = id >> 3, e = (id & 7) * 8;                                 \
            uint32_t so = (uint32_t)(r * 144 + e * 2);                         \
            size_t go = kvb + (size_t)r * D_ + e;                              \
            cpa16(sb + AF_K(st) + so, Kf + go);                                \
            cpa16(sb + AF_V(st) + so, Vf + go);                                \
        }                                                                      \
        cpa_commit();                                                          \
    }
    LOADKV(0, 0);
    if (nkt > 1) LOADKV(1, 1);

    float m0 = -1e30f, m1 = -1e30f, l0 = 0.f, l1 = 0.f;
    float o[8][4];
#pragma unroll
    for (int j = 0; j < 8; j++)
#pragma unroll
        for (int e = 0; e < 4; e++) o[j][e] = 0.f;

    for (int kt = 0; kt < nkt; kt++) {
        const int st = kt % 3;
        if (kt + 2 < nkt) { LOADKV(kt + 2, (kt + 2) % 3); cpa_wait2(); }
        else if (kt + 1 < nkt) cpa_wait1();
        else cpa_wait0();
        __syncthreads();

        if (kt * 64 <= qrow0 + 15) {
            // ---- S = Q K^T ----
            float s[8][4];
#pragma unroll
            for (int j = 0; j < 8; j++)
#pragma unroll
                for (int e = 0; e < 4; e++) s[j][e] = 0.f;

#pragma unroll
            for (int kc = 0; kc < 4; kc++) {
                uint32_t ah[4];
                ldsm_x4(ah, sb + AF_Q + (uint32_t)(wr + arow) * 144 + kc * 32 + ak);
#pragma unroll
                for (int np = 0; np < 4; np++) {
                    uint32_t kb4[4];
                    ldsm_x4(kb4, sb + AF_K(st) + (uint32_t)(np * 16 + brow) * 144 + kc * 32 + bk);
                    mma_f16(s[np * 2],     ah, &kb4[0]);
                    mma_f16(s[np * 2 + 1], ah, &kb4[2]);
                }
            }

            // ---- scale + causal mask (score scale = DH^-0.5 = 1/8) ----
            const int r0 = qrow0 + g, r1 = r0 + 8;
#pragma unroll
            for (int j = 0; j < 8; j++) {
                int c0 = kt * 64 + j * 8 + 2 * tg;
                s[j][0] = (c0     <= r0) ? s[j][0] * 0.125f : -1e30f;
                s[j][1] = (c0 + 1 <= r0) ? s[j][1] * 0.125f : -1e30f;
                s[j][2] = (c0     <= r1) ? s[j][2] * 0.125f : -1e30f;
                s[j][3] = (c0 + 1 <= r1) ? s[j][3] * 0.125f : -1e30f;
            }

            // ---- online softmax ----
            float mx0 = -1e30f, mx1 = -1e30f;
#pragma unroll
            for (int j = 0; j < 8; j++) {
                mx0 = fmaxf(mx0, fmaxf(s[j][0], s[j][1]));
                mx1 = fmaxf(mx1, fmaxf(s[j][2], s[j][3]));
            }
            mx0 = fmaxf(mx0, __shfl_xor_sync(0xffffffffu, mx0, 1));
            mx0 = fmaxf(mx0, __shfl_xor_sync(0xffffffffu, mx0, 2));
            mx1 = fmaxf(mx1, __shfl_xor_sync(0xffffffffu, mx1, 1));
            mx1 = fmaxf(mx1, __shfl_xor_sync(0xffffffffu, mx1, 2));
            float mn0 = fmaxf(m0, mx0), mn1 = fmaxf(m1, mx1);
            float f0 = __expf(m0 - mn0), f1 = __expf(m1 - mn1);
            m0 = mn0; m1 = mn1;
            float rs0 = 0.f, rs1 = 0.f;
#pragma unroll
            for (int j = 0; j < 8; j++) {
                s[j][0] = __expf(s[j][0] - mn0);
                s[j][1] = __expf(s[j][1] - mn0);
                s[j][2] = __expf(s[j][2] - mn1);
                s[j][3] = __expf(s[j][3] - mn1);
                rs0 += s[j][0] + s[j][1];
                rs1 += s[j][2] + s[j][3];
            }
            rs0 += __shfl_xor_sync(0xffffffffu, rs0, 1);
            rs0 += __shfl_xor_sync(0xffffffffu, rs0, 2);
            rs1 += __shfl_xor_sync(0xffffffffu, rs1, 1);
            rs1 += __shfl_xor_sync(0xffffffffu, rs1, 2);
            l0 = l0 * f0 + rs0;
            l1 = l1 * f1 + rs1;
#pragma unroll
            for (int j = 0; j < 8; j++) {
                o[j][0] *= f0; o[j][1] *= f0;
                o[j][2] *= f1; o[j][3] *= f1;
            }

            // ---- O += P V (P packed fp16 in registers) ----
#pragma unroll
            for (int kc = 0; kc < 4; kc++) {
                const int j0 = 2 * kc, j1 = 2 * kc + 1;
                uint32_t pah[4];
                pah[0] = pack_h2(s[j0][0], s[j0][1]);
                pah[1] = pack_h2(s[j0][2], s[j0][3]);
                pah[2] = pack_h2(s[j1][0], s[j1][1]);
                pah[3] = pack_h2(s[j1][2], s[j1][3]);
#pragma unroll
                for (int np = 0; np < 4; np++) {
                    uint32_t vb[4];
                    uint32_t vaddr = (uint32_t)(kc * 16 + vrow) * 144 + np * 32 + vck;
                    ldsm_x4t(vb, sb + AF_V(st) + vaddr);
                    mma_f16(o[np * 2],     pah, &vb[0]);
                    mma_f16(o[np * 2 + 1], pah, &vb[2]);
                }
            }
        }
        __syncthreads();
    }

    // ---- epilogue: normalize, store fp16 ----
    const float inv0 = 1.f / l0, inv1 = 1.f / l1;
    const size_t ob = (size_t)(b * T_ + qrow0) * D_ + h * 64;
#pragma unroll
    for (int j = 0; j < 8; j++) {
        int col = j * 8 + 2 * tg;
        *(half2*)(Af + ob + (size_t)g * D_ + col) =
            __floats2half2_rn(o[j][0] * inv0, o[j][1] * inv0);
        *(half2*)(Af + ob + (size_t)(g + 8) * D_ + col) =
            __floats2half2_rn(o[j][2] * inv1, o[j][3] * inv1);
    }
}

// ---------------------------------------------------------------------------
// Launch. Inputs: 0:x 1:k_cache 2:v_cache 3:mask 4:Wq 5:bq 6:Wk 7:Wv 8:bv 9:Wo 10:bo
// Output: [out | k_cache | v_cache]
// ---------------------------------------------------------------------------
extern "C" void kernel_launch(void* const* d_in, const int* in_sizes, int n_in,
                              void* d_out, int out_size)
{
    (void)in_sizes; (void)n_in; (void)out_size;
    const float* x   = (const float*)d_in[0];
    const float* Wq  = (const float*)d_in[4];
    const float* bq  = (const float*)d_in[5];
    const float* Wk  = (const float*)d_in[6];
    const float* Wv  = (const float*)d_in[7];
    const float* bvp = (const float*)d_in[8];
    const float* Wo  = (const float*)d_in[9];
    const float* bo  = (const float*)d_in[10];

    float* out = (float*)d_out;
    float* kc  = out + (size_t)MTOT * D_;
    float* vc  = kc  + (size_t)MTOT * D_;

    half *Xf, *Wtf, *Qf, *Kf, *Vf, *Af;
    cudaGetSymbolAddress((void**)&Xf,  g_Xf);
    cudaGetSymbolAddress((void**)&Wtf, g_Wtf);
    cudaGetSymbolAddress((void**)&Qf,  g_Qf);
    cudaGetSymbolAddress((void**)&Kf,  g_Kf);
    cudaGetSymbolAddress((void**)&Vf,  g_Vf);
    cudaGetSymbolAddress((void**)&Af,  g_Af);

    const size_t WSZ = (size_t)D_ * D_;
    const int NX = MTOT * D_;

    dim3 tg(D_ / 32, D_ / 32), tb(32, 8);
    transpose_f16_kernel<<<tg, tb>>>(Wq, Wtf + 0 * WSZ);
    transpose_f16_kernel<<<tg, tb>>>(Wk, Wtf + 1 * WSZ);
    transpose_f16_kernel<<<tg, tb>>>(Wv, Wtf + 2 * WSZ);
    transpose_f16_kernel<<<tg, tb>>>(Wo, Wtf + 3 * WSZ);
    tof16_kernel<<<NX / (256 * 4), 256>>>(x, Xf, NX);

    cudaFuncSetAttribute(gemm_f16_kernel,
                         cudaFuncAttributeMaxDynamicSharedMemorySize, F16_SMEM);
    dim3 gg(D_ / 128, MTOT / 128);   // (10, 64)

    gemm_f16_kernel<<<gg, 256, F16_SMEM>>>(Xf, Wtf + 0 * WSZ, bq,      nullptr, Qf);
    gemm_f16_kernel<<<gg, 256, F16_SMEM>>>(Xf, Wtf + 1 * WSZ, nullptr, kc,      Kf);
    gemm_f16_kernel<<<gg, 256, F16_SMEM>>>(Xf, Wtf + 2 * WSZ, bvp,     vc,      Vf);

    cudaFuncSetAttribute(attn_f16_kernel,
                         cudaFuncAttributeMaxDynamicSharedMemorySize, ATTN_SMEM);
    dim3 ga(B_ * H_, T_ / 128);      // (160, 8)
    attn_f16_kernel<<<ga, 256, ATTN_SMEM>>>(Qf, Kf, Vf, Af);

    gemm_f16_kernel<<<gg, 256, F16_SMEM>>>(Af, Wtf + 3 * WSZ, bo, out, nullptr);
}